// round 3
// baseline (speedup 1.0000x reference)
#include <cuda_runtime.h>
#include <cuda_bf16.h>

// CondConv2D: B=16, C_in=C_out=64, H=W=256, E=4, 3x3, stride=1, dil=1, pad=1.
// Pipeline:
//   1) pool_kernel : per-(b,c) spatial mean                      -> g_pooled[16*64]
//   2) mix_kernel  : routing sigmoid + expert-mix of kernels     -> g_wmix[b][ic][tap][oc]
//   3) conv_kernel : register-blocked fp32 direct conv (FFMA)    -> out (NCHW fp32)

#define B_    16
#define CIN   64
#define COUT  64
#define HH    256
#define WW    256
#define NE    4

#define TH    8     // output tile rows
#define TW    32    // output tile cols
#define OCT   32    // output channels per block
#define ICB   16    // input-channel chunk

// Scratch (allocation-free rule: __device__ globals)
__device__ float g_pooled[B_ * CIN];
__device__ float g_wmix[(size_t)B_ * CIN * 9 * COUT];   // [b][ic][tap][oc], 2.36 MB

// ---------------------------------------------------------------------------
// 1) Spatial mean: one block per (b, c). 65536 floats -> 1.
// ---------------------------------------------------------------------------
__global__ __launch_bounds__(256) void pool_kernel(const float* __restrict__ x) {
    int bc = blockIdx.x;  // b*CIN + c
    const float4* p = reinterpret_cast<const float4*>(x + (size_t)bc * HH * WW);
    float s = 0.f;
    for (int i = threadIdx.x; i < HH * WW / 4; i += 256) {
        float4 v = p[i];
        s += (v.x + v.y) + (v.z + v.w);
    }
    __shared__ float sm[256];
    sm[threadIdx.x] = s;
    __syncthreads();
    for (int o = 128; o > 0; o >>= 1) {
        if (threadIdx.x < o) sm[threadIdx.x] += sm[threadIdx.x + o];
        __syncthreads();
    }
    if (threadIdx.x == 0) g_pooled[bc] = sm[0] * (1.f / (HH * WW));
}

// ---------------------------------------------------------------------------
// 2) Routing (sigmoid MLP) + expert-mixed kernels.
//    One block per batch. Output layout [ic][tap][oc] so the conv kernel gets
//    contiguous oc for vectorized smem staging.
// ---------------------------------------------------------------------------
__global__ __launch_bounds__(256) void mix_kernel(const float* __restrict__ weight,  // [E][COUT][CIN][3][3]
                                                  const float* __restrict__ fc_w,    // [E][CIN]
                                                  const float* __restrict__ fc_b) {  // [E]
    int b = blockIdx.x;
    __shared__ float r[NE];
    if (threadIdx.x < NE) {
        int e = threadIdx.x;
        float acc = fc_b[e];
        #pragma unroll 8
        for (int c = 0; c < CIN; c++) acc += g_pooled[b * CIN + c] * fc_w[e * CIN + c];
        r[e] = 1.f / (1.f + expf(-acc));
    }
    __syncthreads();
    float r0 = r[0], r1 = r[1], r2 = r[2], r3 = r[3];

    const size_t estride = (size_t)COUT * CIN * 9;
    for (int idx = threadIdx.x; idx < CIN * 9 * COUT; idx += 256) {
        int ic  = idx / (9 * COUT);
        int tap = (idx / COUT) % 9;
        int oc  = idx % COUT;
        size_t src = ((size_t)oc * CIN + ic) * 9 + tap;   // within one expert
        float v = r0 * weight[src]
                + r1 * weight[src + estride]
                + r2 * weight[src + 2 * estride]
                + r3 * weight[src + 3 * estride];
        g_wmix[(((size_t)b * CIN + ic) * 9 + tap) * COUT + oc] = v;
    }
}

// ---------------------------------------------------------------------------
// 3) Direct conv, register-blocked.
//    Grid: (WW/TW, HH/TH, B_*(COUT/OCT)). Block: 256 threads.
//    Thread (og = tid>>5, sg = tid&31) computes oc = oc0+og*4..+3 at
//    (h = 0..7, w = w0+sg). Weights: warp-uniform LDS.128 broadcast.
//    Inputs: lanes read consecutive columns -> conflict-free LDS.
// ---------------------------------------------------------------------------
__global__ __launch_bounds__(256) void conv_kernel(const float* __restrict__ x,
                                                   float* __restrict__ out) {
    int w0  = blockIdx.x * TW;
    int h0  = blockIdx.y * TH;
    int b   = blockIdx.z >> 1;
    int oc0 = (blockIdx.z & 1) * OCT;

    __shared__ float s_in[ICB][TH + 2][TW + 2];          // 16*10*34*4 = 21760 B
    __shared__ __align__(16) float s_w[ICB][9][OCT];     // 16*9*32*4  = 18432 B

    int tid = threadIdx.x;
    int sg  = tid & 31;   // w offset within tile
    int og  = tid >> 5;   // oc quad: oc0 + og*4 .. +3 (warp-uniform)

    float acc[TH][4];
    #pragma unroll
    for (int h = 0; h < TH; h++) {
        acc[h][0] = 0.f; acc[h][1] = 0.f; acc[h][2] = 0.f; acc[h][3] = 0.f;
    }

    const float* xb = x + (size_t)b * CIN * HH * WW;
    const float* wb = g_wmix + (size_t)b * CIN * 9 * COUT;

    for (int ic0 = 0; ic0 < CIN; ic0 += ICB) {
        // ---- stage input tile (with zero-padding at image borders) ----
        const int IN_ELEMS = ICB * (TH + 2) * (TW + 2);
        for (int idx = tid; idx < IN_ELEMS; idx += 256) {
            int ic  = idx / ((TH + 2) * (TW + 2));
            int rem = idx % ((TH + 2) * (TW + 2));
            int rr  = rem / (TW + 2);
            int cc  = rem % (TW + 2);
            int gh = h0 + rr - 1;
            int gw = w0 + cc - 1;
            float v = 0.f;
            if ((unsigned)gh < HH && (unsigned)gw < WW)
                v = xb[(size_t)(ic0 + ic) * HH * WW + (size_t)gh * WW + gw];
            s_in[ic][rr][cc] = v;
        }
        // ---- stage weight tile [ic][tap][oc0..oc0+31] ----
        const int W_ELEMS = ICB * 9 * OCT;
        for (int idx = tid; idx < W_ELEMS; idx += 256) {
            int ic  = idx / (9 * OCT);
            int rem = idx % (9 * OCT);
            int tap = rem / OCT;
            int j   = rem % OCT;
            s_w[ic][tap][j] = wb[(((size_t)(ic0 + ic)) * 9 + tap) * COUT + oc0 + j];
        }
        __syncthreads();

        // ---- compute ----
        for (int ic = 0; ic < ICB; ic++) {
            #pragma unroll
            for (int kh = 0; kh < 3; kh++) {
                #pragma unroll
                for (int kw = 0; kw < 3; kw++) {
                    float4 wv = *reinterpret_cast<const float4*>(&s_w[ic][kh * 3 + kw][og * 4]);
                    float in[TH];
                    #pragma unroll
                    for (int h = 0; h < TH; h++) in[h] = s_in[ic][h + kh][sg + kw];
                    #pragma unroll
                    for (int h = 0; h < TH; h++) {
                        acc[h][0] += in[h] * wv.x;
                        acc[h][1] += in[h] * wv.y;
                        acc[h][2] += in[h] * wv.z;
                        acc[h][3] += in[h] * wv.w;
                    }
                }
            }
        }
        __syncthreads();
    }

    // ---- write NCHW fp32; lanes of a warp write consecutive w (coalesced) ----
    #pragma unroll
    for (int j = 0; j < 4; j++) {
        int oc = oc0 + og * 4 + j;
        float* op = out + (((size_t)b * COUT + oc) * HH + h0) * WW + w0 + sg;
        #pragma unroll
        for (int h = 0; h < TH; h++) op[(size_t)h * WW] = acc[h][j];
    }
}

// ---------------------------------------------------------------------------
// Launch
// ---------------------------------------------------------------------------
extern "C" void kernel_launch(void* const* d_in, const int* in_sizes, int n_in,
                              void* d_out, int out_size) {
    const float* inputs = (const float*)d_in[0];   // [16,64,256,256]
    const float* weight = (const float*)d_in[1];   // [4,64,64,3,3]
    const float* fc_w   = (const float*)d_in[2];   // [4,64]
    const float* fc_b   = (const float*)d_in[3];   // [4]
    float* out = (float*)d_out;                    // [16,64,256,256]

    pool_kernel<<<B_ * CIN, 256>>>(inputs);
    mix_kernel<<<B_, 256>>>(weight, fc_w, fc_b);

    dim3 grid(WW / TW, HH / TH, B_ * (COUT / OCT));  // (8, 32, 32)
    conv_kernel<<<grid, 256>>>(inputs, out);
}

// round 4
// speedup vs baseline: 1.2034x; 1.2034x over previous
#include <cuda_runtime.h>
#include <cuda_bf16.h>

// CondConv2D: B=16, C_in=C_out=64, H=W=256, E=4, 3x3, stride=1, dil=1, pad=1.
//   1) pool_kernel : per-(b,c) spatial mean
//   2) mix_kernel  : routing sigmoid + expert-mix -> g_wmix[b][ic][tap][oc]
//   3) conv_kernel : register-blocked direct conv on the packed fma.rn.f32x2
//                    pipe (2 MACs/lane/instr; ptxas never emits it from C++).

#define B_    16
#define CIN   64
#define COUT  64
#define HH    256
#define WW    256
#define NE    4

#define TH    8     // output rows per block
#define TW    32    // output cols per block (1 per lane)
#define OCT   64    // output channels per block (8 per thread, paired f32x2)
#define ICB   8     // input-channel chunk (keeps static smem < 48KB)

__device__ float g_pooled[B_ * CIN];
__device__ float g_wmix[(size_t)B_ * CIN * 9 * COUT];   // [b][ic][tap][oc]

typedef unsigned long long ull;

__device__ __forceinline__ ull pack2(float lo, float hi) {
    ull r;
    asm("mov.b64 %0, {%1, %2};" : "=l"(r) : "f"(lo), "f"(hi));
    return r;
}
__device__ __forceinline__ void unpack2(float& lo, float& hi, ull v) {
    asm("mov.b64 {%0, %1}, %2;" : "=f"(lo), "=f"(hi) : "l"(v));
}
__device__ __forceinline__ void fma2(ull& d, ull a, ull b) {
    asm("fma.rn.f32x2 %0, %1, %2, %3;" : "=l"(d) : "l"(a), "l"(b), "l"(d));
}

// ---------------------------------------------------------------------------
// 1) Spatial mean: one block per (b, c).
// ---------------------------------------------------------------------------
__global__ __launch_bounds__(256) void pool_kernel(const float* __restrict__ x) {
    int bc = blockIdx.x;
    const float4* p = reinterpret_cast<const float4*>(x + (size_t)bc * HH * WW);
    float s = 0.f;
    for (int i = threadIdx.x; i < HH * WW / 4; i += 256) {
        float4 v = p[i];
        s += (v.x + v.y) + (v.z + v.w);
    }
    __shared__ float sm[256];
    sm[threadIdx.x] = s;
    __syncthreads();
    for (int o = 128; o > 0; o >>= 1) {
        if (threadIdx.x < o) sm[threadIdx.x] += sm[threadIdx.x + o];
        __syncthreads();
    }
    if (threadIdx.x == 0) g_pooled[bc] = sm[0] * (1.f / (HH * WW));
}

// ---------------------------------------------------------------------------
// 2) Routing + expert-mixed kernels -> [b][ic][tap][oc] (oc contiguous).
// ---------------------------------------------------------------------------
__global__ __launch_bounds__(256) void mix_kernel(const float* __restrict__ weight,
                                                  const float* __restrict__ fc_w,
                                                  const float* __restrict__ fc_b) {
    int b = blockIdx.x;
    __shared__ float r[NE];
    if (threadIdx.x < NE) {
        int e = threadIdx.x;
        float acc = fc_b[e];
        #pragma unroll 8
        for (int c = 0; c < CIN; c++) acc += g_pooled[b * CIN + c] * fc_w[e * CIN + c];
        r[e] = 1.f / (1.f + expf(-acc));
    }
    __syncthreads();
    float r0 = r[0], r1 = r[1], r2 = r[2], r3 = r[3];

    const size_t estride = (size_t)COUT * CIN * 9;
    for (int idx = threadIdx.x; idx < CIN * 9 * COUT; idx += 256) {
        int ic  = idx / (9 * COUT);
        int tap = (idx / COUT) % 9;
        int oc  = idx % COUT;
        size_t src = ((size_t)oc * CIN + ic) * 9 + tap;
        float v = r0 * weight[src]
                + r1 * weight[src + estride]
                + r2 * weight[src + 2 * estride]
                + r3 * weight[src + 3 * estride];
        g_wmix[(((size_t)b * CIN + ic) * 9 + tap) * COUT + oc] = v;
    }
}

// ---------------------------------------------------------------------------
// 3) Direct conv on the f32x2 pipe.
//    Grid: (WW/TW, HH/TH, B). Block: 256 threads.
//    Thread (og = tid>>5, sg = tid&31): oc = og*8 .. og*8+7 (4 f32x2 pairs),
//    w = w0+sg, h = 0..7  -> 32 f32x2 accumulators (64 outputs).
//    Weights: oc-pairs are contiguous -> LDS.64 gives the packed operand.
//    Inputs: scalar LDS (lanes = consecutive w, conflict-free), duplicated
//    into both f32x2 halves once per row.
// ---------------------------------------------------------------------------
__global__ __launch_bounds__(256, 2) void conv_kernel(const float* __restrict__ x,
                                                      float* __restrict__ out) {
    int w0 = blockIdx.x * TW;
    int h0 = blockIdx.y * TH;
    int b  = blockIdx.z;

    __shared__ float s_in[ICB][TH + 2][TW + 2];          // 8*10*34*4 = 10880 B
    __shared__ __align__(16) float s_w[ICB][9][OCT];     // 8*9*64*4  = 18432 B

    int tid = threadIdx.x;
    int sg  = tid & 31;
    int og  = tid >> 5;   // 0..7, oc base = og*8 (warp-uniform)

    ull acc2[TH][4];
    #pragma unroll
    for (int h = 0; h < TH; h++)
        #pragma unroll
        for (int j = 0; j < 4; j++) acc2[h][j] = 0ULL;

    const float* xb = x + (size_t)b * CIN * HH * WW;
    const float* wb = g_wmix + (size_t)b * CIN * 9 * COUT;

    for (int ic0 = 0; ic0 < CIN; ic0 += ICB) {
        // ---- stage input tile (zero-padded at borders) ----
        const int IN_ELEMS = ICB * (TH + 2) * (TW + 2);   // 2720
        for (int idx = tid; idx < IN_ELEMS; idx += 256) {
            int ic  = idx / ((TH + 2) * (TW + 2));
            int rem = idx % ((TH + 2) * (TW + 2));
            int rr  = rem / (TW + 2);
            int cc  = rem % (TW + 2);
            int gh = h0 + rr - 1;
            int gw = w0 + cc - 1;
            float v = 0.f;
            if ((unsigned)gh < HH && (unsigned)gw < WW)
                v = xb[(size_t)(ic0 + ic) * HH * WW + (size_t)gh * WW + gw];
            s_in[ic][rr][cc] = v;
        }
        // ---- stage weights: contiguous copy of [ICB][9][64] ----
        {
            const float4* src = reinterpret_cast<const float4*>(wb + (size_t)ic0 * 9 * COUT);
            float4* dst = reinterpret_cast<float4*>(&s_w[0][0][0]);
            const int W_VEC = ICB * 9 * OCT / 4;          // 1152
            for (int idx = tid; idx < W_VEC; idx += 256) dst[idx] = src[idx];
        }
        __syncthreads();

        for (int ic = 0; ic < ICB; ic++) {
            #pragma unroll
            for (int kw = 0; kw < 3; kw++) {
                // 10 input rows for this (ic, kw), duplicated into f32x2
                ull in2[TH + 2];
                #pragma unroll
                for (int r = 0; r < TH + 2; r++) {
                    float v = s_in[ic][r][sg + kw];
                    in2[r] = pack2(v, v);
                }
                #pragma unroll
                for (int kh = 0; kh < 3; kh++) {
                    const ull* wp = reinterpret_cast<const ull*>(&s_w[ic][kh * 3 + kw][og * 8]);
                    ull w2_0 = wp[0], w2_1 = wp[1], w2_2 = wp[2], w2_3 = wp[3];
                    #pragma unroll
                    for (int h = 0; h < TH; h++) {
                        fma2(acc2[h][0], in2[h + kh], w2_0);
                        fma2(acc2[h][1], in2[h + kh], w2_1);
                        fma2(acc2[h][2], in2[h + kh], w2_2);
                        fma2(acc2[h][3], in2[h + kh], w2_3);
                    }
                }
            }
        }
        __syncthreads();
    }

    // ---- epilogue: unpack + coalesced stores (lanes = consecutive w) ----
    #pragma unroll
    for (int j = 0; j < 4; j++) {
        int oc = og * 8 + 2 * j;
        float* op0 = out + (((size_t)b * COUT + oc)     * HH + h0) * WW + w0 + sg;
        float* op1 = out + (((size_t)b * COUT + oc + 1) * HH + h0) * WW + w0 + sg;
        #pragma unroll
        for (int h = 0; h < TH; h++) {
            float lo, hi;
            unpack2(lo, hi, acc2[h][j]);
            op0[(size_t)h * WW] = lo;
            op1[(size_t)h * WW] = hi;
        }
    }
}

// ---------------------------------------------------------------------------
extern "C" void kernel_launch(void* const* d_in, const int* in_sizes, int n_in,
                              void* d_out, int out_size) {
    const float* inputs = (const float*)d_in[0];   // [16,64,256,256]
    const float* weight = (const float*)d_in[1];   // [4,64,64,3,3]
    const float* fc_w   = (const float*)d_in[2];   // [4,64]
    const float* fc_b   = (const float*)d_in[3];   // [4]
    float* out = (float*)d_out;                    // [16,64,256,256]

    pool_kernel<<<B_ * CIN, 256>>>(inputs);
    mix_kernel<<<B_, 256>>>(weight, fc_w, fc_b);

    dim3 grid(WW / TW, HH / TH, B_);               // (8, 32, 16)
    conv_kernel<<<grid, 256>>>(inputs, out);
}

// round 6
// speedup vs baseline: 2.3751x; 1.9737x over previous
#include <cuda_runtime.h>
#include <cuda_bf16.h>
#include <cstdint>

// CondConv2D: B=16, C=64, H=W=256, E=4, 3x3, pad=1.
//   1) pool_kernel : spatial mean
//   2) mix_kernel  : routing + expert mix -> g_wmix[b][chunk18][k32][oc64], tf32-rounded
//   3) conv_kernel : implicit GEMM on legacy mma.sync (tf32, baseline PTX —
//                    tcgen05 is 'a'-feature-gated and the harness targets sm_103).
//      Per CTA: D[128 pix][64 oc], K=576 in 18 chunks of 32 (chunk = ic-half x tap).
//      8 warps, each 32pix x 32oc = 2x4 m16n8k8 tiles, 32 fp32 accums.

#define B_     16
#define CIN    64
#define COUT   64
#define HH     256
#define WW     256
#define HW     (HH * WW)
#define NE     4
#define NCHUNK 18
#define MTILE  128

// smem rows padded to 8 floats so fragment loads hit all 32 banks:
// bank = (8*t + g) & 31 over the warp -> conflict-free.
#define RA 136   // 128 pix + 8 pad
#define RB 72    // 64 oc + 8 pad

__device__ float g_pooled[B_ * CIN];
__device__ float g_wmix[(size_t)B_ * NCHUNK * 32 * COUT];  // [b][chunk][j][oc]

__device__ __forceinline__ uint32_t to_tf32(float x) {
    uint32_t t;
    asm("cvt.rna.tf32.f32 %0, %1;" : "=r"(t) : "f"(x));
    return t;
}

__device__ __forceinline__ void mma_tf32(float& d0, float& d1, float& d2, float& d3,
                                         uint32_t a0, uint32_t a1, uint32_t a2, uint32_t a3,
                                         uint32_t b0, uint32_t b1) {
    asm volatile(
        "mma.sync.aligned.m16n8k8.row.col.f32.tf32.tf32.f32 "
        "{%0,%1,%2,%3}, {%4,%5,%6,%7}, {%8,%9}, {%0,%1,%2,%3};"
        : "+f"(d0), "+f"(d1), "+f"(d2), "+f"(d3)
        : "r"(a0), "r"(a1), "r"(a2), "r"(a3), "r"(b0), "r"(b1));
}

// ---------------- 1) pool ----------------
__global__ __launch_bounds__(256) void pool_kernel(const float* __restrict__ x) {
    int bc = blockIdx.x;
    const float4* p = reinterpret_cast<const float4*>(x + (size_t)bc * HW);
    float s = 0.f;
    for (int i = threadIdx.x; i < HW / 4; i += 256) {
        float4 v = p[i];
        s += (v.x + v.y) + (v.z + v.w);
    }
    __shared__ float sm[256];
    sm[threadIdx.x] = s;
    __syncthreads();
    for (int o = 128; o > 0; o >>= 1) {
        if (threadIdx.x < o) sm[threadIdx.x] += sm[threadIdx.x + o];
        __syncthreads();
    }
    if (threadIdx.x == 0) g_pooled[bc] = sm[0] * (1.f / HW);
}

// ---------------- 2) mix -> [b][chunk][j][oc] tf32 ----------------
__global__ __launch_bounds__(256) void mix_kernel(const float* __restrict__ weight,  // [E][OC][IC][3][3]
                                                  const float* __restrict__ fc_w,
                                                  const float* __restrict__ fc_b) {
    int b = blockIdx.x;
    __shared__ float r[NE];
    if (threadIdx.x < NE) {
        int e = threadIdx.x;
        float acc = fc_b[e];
        #pragma unroll 8
        for (int c = 0; c < CIN; c++) acc += g_pooled[b * CIN + c] * fc_w[e * CIN + c];
        r[e] = 1.f / (1.f + expf(-acc));
    }
    __syncthreads();
    float r0 = r[0], r1 = r[1], r2 = r[2], r3 = r[3];

    const size_t estride = (size_t)COUT * CIN * 9;
    for (int idx = threadIdx.x; idx < NCHUNK * 32 * COUT; idx += 256) {
        int oc = idx & 63;
        int j  = (idx >> 6) & 31;
        int c  = idx >> 11;          // 0..17
        int t  = c % 9;              // kh*3+kw
        int ih = c / 9;
        int ic = ih * 32 + j;
        size_t src = ((size_t)oc * CIN + ic) * 9 + t;
        float v = r0 * weight[src]
                + r1 * weight[src + estride]
                + r2 * weight[src + 2 * estride]
                + r3 * weight[src + 3 * estride];
        g_wmix[(size_t)b * (NCHUNK * 32 * COUT) + idx] = __uint_as_float(to_tf32(v));
    }
}

// ---------------- 3) implicit-GEMM conv on mma.sync tf32 ----------------
__global__ __launch_bounds__(256, 2) void conv_kernel(const float* __restrict__ x,
                                                      float* __restrict__ out) {
    __shared__ uint32_t A_s[32][RA];   // [k][pix]  17408 B
    __shared__ uint32_t B_s[32][RB];   // [k][oc]    9216 B

    const int tid = threadIdx.x;
    const int wid = tid >> 5;
    const int lid = tid & 31;
    const int g = lid >> 2;            // group id (0..7)
    const int t = lid & 3;             // thread-in-group (0..3)
    const int warpM = wid & 3;         // pix group of 32
    const int warpN = wid >> 2;        // oc  group of 32

    const int w0 = blockIdx.x * MTILE;
    const int h  = blockIdx.y;
    const int b  = blockIdx.z;

    const float* xb = x + (size_t)b * CIN * HW;
    const float* wb = g_wmix + (size_t)b * NCHUNK * 32 * COUT;

    // staging geometry (constant per thread)
    const int pA = tid & 127;          // pix column
    const int j0 = tid >> 7;           // k row base (0/1), rows j0 + 2i
    const int jB = tid >> 6;           // B k row base (0..3), rows jB + 4i
    const int ocB = tid & 63;

    float d[2][4][4];
    #pragma unroll
    for (int mt = 0; mt < 2; mt++)
        #pragma unroll
        for (int nt = 0; nt < 4; nt++)
            #pragma unroll
            for (int k = 0; k < 4; k++) d[mt][nt][k] = 0.f;

    float aReg[16];
    float bReg[8];

    // ---- prefetch chunk 0 ----
    {
        const int c = 0, tap = 0, ih = 0, kh = 0, kw = 0;
        (void)c; (void)tap;
        int hp = h + kh - 1;
        int wp = w0 + pA + kw - 1;
        bool v = ((unsigned)hp < HH) && ((unsigned)wp < WW);
        const float* abase = xb + (size_t)(ih * 32 + j0) * HW + (size_t)hp * WW + wp;
        #pragma unroll
        for (int i = 0; i < 16; i++) aReg[i] = v ? __ldg(abase + (size_t)(2 * i) * HW) : 0.f;
        const float* bbase = wb + jB * 64 + ocB;
        #pragma unroll
        for (int i = 0; i < 8; i++) bReg[i] = __ldg(bbase + i * 256);
    }

    for (int c = 0; c < NCHUNK; c++) {
        __syncthreads();   // previous compute done; smem reusable
        // ---- store staged regs to smem (A converted to tf32 here) ----
        #pragma unroll
        for (int i = 0; i < 16; i++) A_s[j0 + 2 * i][pA] = to_tf32(aReg[i]);
        #pragma unroll
        for (int i = 0; i < 8; i++) B_s[jB + 4 * i][ocB] = __float_as_uint(bReg[i]);
        __syncthreads();

        // ---- issue prefetch for chunk c+1 ----
        if (c + 1 < NCHUNK) {
            int cn = c + 1;
            int tap = cn % 9, ih = cn / 9;
            int kh = tap / 3, kw = tap % 3;
            int hp = h + kh - 1;
            int wp = w0 + pA + kw - 1;
            bool v = ((unsigned)hp < HH) && ((unsigned)wp < WW);
            const float* abase = xb + (size_t)(ih * 32 + j0) * HW + (size_t)hp * WW + wp;
            #pragma unroll
            for (int i = 0; i < 16; i++) aReg[i] = v ? __ldg(abase + (size_t)(2 * i) * HW) : 0.f;
            const float* bbase = wb + (size_t)cn * 2048 + jB * 64 + ocB;
            #pragma unroll
            for (int i = 0; i < 8; i++) bReg[i] = __ldg(bbase + i * 256);
        }

        // ---- compute chunk c: 4 k-steps of 8 ----
        #pragma unroll
        for (int ks = 0; ks < 4; ks++) {
            const int kb = ks * 8;
            uint32_t a[2][4];
            #pragma unroll
            for (int mt = 0; mt < 2; mt++) {
                int mb = warpM * 32 + mt * 16 + g;
                a[mt][0] = A_s[kb + t][mb];
                a[mt][1] = A_s[kb + t][mb + 8];
                a[mt][2] = A_s[kb + t + 4][mb];
                a[mt][3] = A_s[kb + t + 4][mb + 8];
            }
            #pragma unroll
            for (int nt = 0; nt < 4; nt++) {
                int nb = warpN * 32 + nt * 8 + g;
                uint32_t b0 = B_s[kb + t][nb];
                uint32_t b1 = B_s[kb + t + 4][nb];
                #pragma unroll
                for (int mt = 0; mt < 2; mt++)
                    mma_tf32(d[mt][nt][0], d[mt][nt][1], d[mt][nt][2], d[mt][nt][3],
                             a[mt][0], a[mt][1], a[mt][2], a[mt][3], b0, b1);
            }
        }
    }

    // ---- epilogue: d0:(oc,pix) d1:(oc+1,pix) d2:(oc,pix+8) d3:(oc+1,pix+8) ----
    #pragma unroll
    for (int nt = 0; nt < 4; nt++) {
        int oc = warpN * 32 + nt * 8 + 2 * t;
        #pragma unroll
        for (int mt = 0; mt < 2; mt++) {
            int pix = w0 + warpM * 32 + mt * 16 + g;
            float* o0 = out + (((size_t)b * COUT + oc) * HH + h) * WW + pix;
            float* o1 = o0 + HW;   // oc + 1
            o0[0] = d[mt][nt][0];
            o1[0] = d[mt][nt][1];
            o0[8] = d[mt][nt][2];
            o1[8] = d[mt][nt][3];
        }
    }
}

// ---------------- launch ----------------
extern "C" void kernel_launch(void* const* d_in, const int* in_sizes, int n_in,
                              void* d_out, int out_size) {
    const float* inputs = (const float*)d_in[0];   // [16,64,256,256]
    const float* weight = (const float*)d_in[1];   // [4,64,64,3,3]
    const float* fc_w   = (const float*)d_in[2];   // [4,64]
    const float* fc_b   = (const float*)d_in[3];   // [4]
    float* out = (float*)d_out;                    // [16,64,256,256]

    pool_kernel<<<B_ * CIN, 256>>>(inputs);
    mix_kernel<<<B_, 256>>>(weight, fc_w, fc_b);
    conv_kernel<<<dim3(WW / MTILE, HH, B_), 256>>>(inputs, out);
}

// round 8
// speedup vs baseline: 3.0942x; 1.3028x over previous
#include <cuda_runtime.h>
#include <cuda_bf16.h>
#include <cstdint>

// CondConv2D: B=16, C=64, H=W=256, E=4, 3x3, pad=1.
//   1) pool_kernel : spatial mean
//   2) mix_kernel  : routing + expert mix -> g_wmix[b][chunk18][k32][oc64] (tf32)
//   3) conv_kernel : implicit GEMM on legacy mma.sync tf32.
//      K restructured as 6 stages (ih x kh); each stage = one halo'd A tile
//      [32][130] reused for kw=0,1,2 via column-shifted fragment reads.
//      cp.async double-buffered; 8 warps x (32pix x 32oc) per 128x64 CTA tile.

#define B_     16
#define CIN    64
#define COUT   64
#define HH     256
#define WW     256
#define HW     (HH * WW)
#define NE     4
#define NCHUNK 18
#define MTILE  128

#define RA 136   // halo row: idx 3..132 = pix -1..128 ; 136 % 32 == 8 -> conflict-free
#define RB 72
#define A_BUF (32 * RA)            // 4352 u32 per buffer
#define B_BUF (3 * 32 * RB)        // 6912 u32 per buffer
#define SMEM_U32 (2 * A_BUF + 2 * B_BUF)
#define SMEM_BYTES (SMEM_U32 * 4)  // 90112

__device__ float g_pooled[B_ * CIN];
__device__ __align__(16) float g_wmix[(size_t)B_ * NCHUNK * 32 * COUT];  // [b][chunk][j][oc]

__device__ __forceinline__ uint32_t to_tf32(float x) {
    uint32_t t;
    asm("cvt.rna.tf32.f32 %0, %1;" : "=r"(t) : "f"(x));
    return t;
}

__device__ __forceinline__ void mma_tf32(float& d0, float& d1, float& d2, float& d3,
                                         uint32_t a0, uint32_t a1, uint32_t a2, uint32_t a3,
                                         uint32_t b0, uint32_t b1) {
    asm volatile(
        "mma.sync.aligned.m16n8k8.row.col.f32.tf32.tf32.f32 "
        "{%0,%1,%2,%3}, {%4,%5,%6,%7}, {%8,%9}, {%0,%1,%2,%3};"
        : "+f"(d0), "+f"(d1), "+f"(d2), "+f"(d3)
        : "r"(a0), "r"(a1), "r"(a2), "r"(a3), "r"(b0), "r"(b1));
}

// ---------------- 1) pool ----------------
__global__ __launch_bounds__(256) void pool_kernel(const float* __restrict__ x) {
    int bc = blockIdx.x;
    const float4* p = reinterpret_cast<const float4*>(x + (size_t)bc * HW);
    float s = 0.f;
    for (int i = threadIdx.x; i < HW / 4; i += 256) {
        float4 v = p[i];
        s += (v.x + v.y) + (v.z + v.w);
    }
    __shared__ float sm[256];
    sm[threadIdx.x] = s;
    __syncthreads();
    for (int o = 128; o > 0; o >>= 1) {
        if (threadIdx.x < o) sm[threadIdx.x] += sm[threadIdx.x + o];
        __syncthreads();
    }
    if (threadIdx.x == 0) g_pooled[bc] = sm[0] * (1.f / HW);
}

// ---------------- 2) mix -> [b][chunk][j][oc] tf32 ----------------
__global__ __launch_bounds__(256) void mix_kernel(const float* __restrict__ weight,  // [E][OC][IC][3][3]
                                                  const float* __restrict__ fc_w,
                                                  const float* __restrict__ fc_b) {
    int b = blockIdx.x;
    __shared__ float r[NE];
    if (threadIdx.x < NE) {
        int e = threadIdx.x;
        float acc = fc_b[e];
        #pragma unroll 8
        for (int c = 0; c < CIN; c++) acc += g_pooled[b * CIN + c] * fc_w[e * CIN + c];
        r[e] = 1.f / (1.f + expf(-acc));
    }
    __syncthreads();
    float r0 = r[0], r1 = r[1], r2 = r[2], r3 = r[3];

    const size_t estride = (size_t)COUT * CIN * 9;
    for (int idx = threadIdx.x; idx < NCHUNK * 32 * COUT; idx += 256) {
        int oc = idx & 63;
        int j  = (idx >> 6) & 31;
        int c  = idx >> 11;          // 0..17
        int t  = c % 9;              // kh*3+kw
        int ih = c / 9;
        int ic = ih * 32 + j;
        size_t src = ((size_t)oc * CIN + ic) * 9 + t;
        float v = r0 * weight[src]
                + r1 * weight[src + estride]
                + r2 * weight[src + 2 * estride]
                + r3 * weight[src + 3 * estride];
        g_wmix[(size_t)b * (NCHUNK * 32 * COUT) + idx] = __uint_as_float(to_tf32(v));
    }
}

// ---------------- 3) implicit-GEMM conv, cp.async pipelined ----------------
__global__ __launch_bounds__(256, 2) void conv_kernel(const float* __restrict__ x,
                                                      float* __restrict__ out) {
    extern __shared__ uint32_t smem[];
    uint32_t* A_base = smem;                  // [2][32][RA]
    uint32_t* B_base = smem + 2 * A_BUF;      // [2][3][32][RB]

    const int tid = threadIdx.x;
    const int wid = tid >> 5;
    const int lid = tid & 31;
    const int g = lid >> 2;            // 0..7
    const int t = lid & 3;             // 0..3
    const int warpM = wid & 3;
    const int warpN = wid >> 2;

    const int w0 = blockIdx.x * MTILE;
    const int h  = blockIdx.y;
    const int b  = blockIdx.z;

    const float* xb = x + (size_t)b * CIN * HW;
    const float* wb = g_wmix + (size_t)b * NCHUNK * 32 * COUT;

    uint32_t sbase;
    asm("{ .reg .u64 tt; cvta.to.shared.u64 tt, %1; cvt.u32.u64 %0, tt; }" : "=r"(sbase) : "l"(smem));

    // stage st = ih*3 + kh
    auto issue = [&](int st, int buf) {
        int ih = st / 3, kh = st % 3;
        int hp = h + kh - 1;
        bool hv = (unsigned)hp < HH;
        int hpc = hv ? hp : 0;
        // A interior: pix w0..w0+127 -> idx 4..131 (16B aligned both sides)
        #pragma unroll
        for (int i = 0; i < 4; i++) {
            int idx = tid + 256 * i;          // 0..1023
            int k = idx >> 5, q = idx & 31;
            const float* src = xb + (size_t)(ih * 32 + k) * HW + (size_t)hpc * WW + w0 + q * 4;
            uint32_t dst = sbase + (uint32_t)((buf * A_BUF + k * RA + 4 + q * 4) * 4);
            uint32_t sz = hv ? 16u : 0u;
            asm volatile("cp.async.cg.shared.global [%0], [%1], 16, %2;"
                         :: "r"(dst), "l"(src), "r"(sz) : "memory");
        }
        // A edges: left (pix w0-1 -> idx 3), right (pix w0+128 -> idx 132)
        if (tid < 64) {
            int k = tid & 31, side = tid >> 5;
            int wp = side ? (w0 + 128) : (w0 - 1);
            bool v = hv && ((unsigned)wp < WW);
            const float* src = xb + (size_t)(ih * 32 + k) * HW + (size_t)hpc * WW + (v ? wp : 0);
            uint32_t dst = sbase + (uint32_t)((buf * A_BUF + k * RA + (side ? 132 : 3)) * 4);
            uint32_t sz = v ? 4u : 0u;
            asm volatile("cp.async.ca.shared.global [%0], [%1], 4, %2;"
                         :: "r"(dst), "l"(src), "r"(sz) : "memory");
        }
        // B: 3 contiguous chunks (kw=0..2) = 6144 floats
        const float* bsrc = wb + (size_t)(ih * 9 + kh * 3) * 2048;
        #pragma unroll
        for (int i = 0; i < 6; i++) {
            int n = tid + 256 * i;            // 0..1535
            int kw = n >> 9, rem = n & 511;
            int k = rem >> 4, q = rem & 15;
            uint32_t dst = sbase + (uint32_t)((2 * A_BUF + buf * B_BUF + kw * (32 * RB) + k * RB + q * 4) * 4);
            asm volatile("cp.async.cg.shared.global [%0], [%1], 16;"
                         :: "r"(dst), "l"(bsrc + n * 4) : "memory");
        }
        asm volatile("cp.async.commit_group;" ::: "memory");
    };

    float d[2][4][4];
    #pragma unroll
    for (int mt = 0; mt < 2; mt++)
        #pragma unroll
        for (int nt = 0; nt < 4; nt++)
            #pragma unroll
            for (int k = 0; k < 4; k++) d[mt][nt][k] = 0.f;

    issue(0, 0);

    for (int st = 0; st < 6; st++) {
        asm volatile("cp.async.wait_group 0;" ::: "memory");
        __syncthreads();
        if (st + 1 < 6) issue(st + 1, (st + 1) & 1);

        const int buf = st & 1;
        const uint32_t* Ab = A_base + buf * A_BUF;
        #pragma unroll
        for (int kw = 0; kw < 3; kw++) {
            const uint32_t* Bb = B_base + buf * B_BUF + kw * (32 * RB);
            #pragma unroll
            for (int ks = 0; ks < 4; ks++) {
                const int kb = ks * 8;
                uint32_t a[2][4];
                #pragma unroll
                for (int mt = 0; mt < 2; mt++) {
                    int mb = warpM * 32 + mt * 16 + g + kw + 3;
                    a[mt][0] = to_tf32(__uint_as_float(Ab[(kb + t) * RA + mb]));
                    a[mt][1] = to_tf32(__uint_as_float(Ab[(kb + t) * RA + mb + 8]));
                    a[mt][2] = to_tf32(__uint_as_float(Ab[(kb + t + 4) * RA + mb]));
                    a[mt][3] = to_tf32(__uint_as_float(Ab[(kb + t + 4) * RA + mb + 8]));
                }
                #pragma unroll
                for (int nt = 0; nt < 4; nt++) {
                    int nb = warpN * 32 + nt * 8 + g;
                    uint32_t b0 = Bb[(kb + t) * RB + nb];
                    uint32_t b1 = Bb[(kb + t + 4) * RB + nb];
                    #pragma unroll
                    for (int mt = 0; mt < 2; mt++)
                        mma_tf32(d[mt][nt][0], d[mt][nt][1], d[mt][nt][2], d[mt][nt][3],
                                 a[mt][0], a[mt][1], a[mt][2], a[mt][3], b0, b1);
                }
            }
        }
    }

    // ---- epilogue (same mapping as before) ----
    #pragma unroll
    for (int nt = 0; nt < 4; nt++) {
        int oc = warpN * 32 + nt * 8 + 2 * t;
        #pragma unroll
        for (int mt = 0; mt < 2; mt++) {
            int pix = w0 + warpM * 32 + mt * 16 + g;
            float* o0 = out + (((size_t)b * COUT + oc) * HH + h) * WW + pix;
            float* o1 = o0 + HW;
            o0[0] = d[mt][nt][0];
            o1[0] = d[mt][nt][1];
            o0[8] = d[mt][nt][2];
            o1[8] = d[mt][nt][3];
        }
    }
}

// ---------------- launch ----------------
extern "C" void kernel_launch(void* const* d_in, const int* in_sizes, int n_in,
                              void* d_out, int out_size) {
    const float* inputs = (const float*)d_in[0];   // [16,64,256,256]
    const float* weight = (const float*)d_in[1];   // [4,64,64,3,3]
    const float* fc_w   = (const float*)d_in[2];   // [4,64]
    const float* fc_b   = (const float*)d_in[3];   // [4]
    float* out = (float*)d_out;                    // [16,64,256,256]

    static int attr_set = 0;
    if (!attr_set) {
        cudaFuncSetAttribute(conv_kernel, cudaFuncAttributeMaxDynamicSharedMemorySize, SMEM_BYTES);
        attr_set = 1;
    }

    pool_kernel<<<B_ * CIN, 256>>>(inputs);
    mix_kernel<<<B_, 256>>>(weight, fc_w, fc_b);
    conv_kernel<<<dim3(WW / MTILE, HH, B_), 256, SMEM_BYTES>>>(inputs, out);
}

// round 9
// speedup vs baseline: 4.3366x; 1.4015x over previous
#include <cuda_runtime.h>
#include <cuda_bf16.h>
#include <cuda_fp16.h>
#include <cstdint>

// CondConv2D: B=16, C=64, H=W=256, E=4, 3x3, pad=1.
//   1) pool_kernel : spatial mean
//   2) mix_kernel  : routing + expert mix -> packed fp16x2 weights
//                    g_wmix[b][stage6][kw3][kp16][oc64] (u32 = ic-pair)
//   3) conv_kernel : implicit GEMM on mma.sync.m16n8k16.f16 (f32 accum).
//      fp16 has the same 11-bit mantissa as tf32 -> same accuracy, 2x MACs/instr.
//      6 stages (ih x kh), halo'd A tile reused for kw via column shifts.

#define B_     16
#define CIN    64
#define COUT   64
#define HH     256
#define WW     256
#define HW     (HH * WW)
#define NE     4
#define MTILE  128

#define RA 136           // pix cols (u32 words); idx 3..132 = pix -1..128; 136%32==8
#define RB 72            // oc cols + pad (u32 words); 72%32==8
#define A_BUFW (16 * RA)         // 2176 u32 / buffer
#define B_BUFW (3 * 16 * RB)     // 3456 u32 / buffer

__device__ float g_pooled[B_ * CIN];
// packed fp16x2 mixed weights: [b][stage 6][kw 3][kp 16][oc 64]
__device__ __align__(16) uint32_t g_wmix[(size_t)B_ * 6 * 3 * 16 * COUT];

__device__ __forceinline__ void mma_f16(float& d0, float& d1, float& d2, float& d3,
                                        uint32_t a0, uint32_t a1, uint32_t a2, uint32_t a3,
                                        uint32_t b0, uint32_t b1) {
    asm volatile(
        "mma.sync.aligned.m16n8k16.row.col.f32.f16.f16.f32 "
        "{%0,%1,%2,%3}, {%4,%5,%6,%7}, {%8,%9}, {%0,%1,%2,%3};"
        : "+f"(d0), "+f"(d1), "+f"(d2), "+f"(d3)
        : "r"(a0), "r"(a1), "r"(a2), "r"(a3), "r"(b0), "r"(b1));
}

__device__ __forceinline__ uint32_t packh2(float lo, float hi) {
    __half2 h = __floats2half2_rn(lo, hi);   // .x = lo (even ic), .y = hi (odd ic)
    return *reinterpret_cast<uint32_t*>(&h);
}

// ---------------- 1) pool ----------------
__global__ __launch_bounds__(256) void pool_kernel(const float* __restrict__ x) {
    int bc = blockIdx.x;
    const float4* p = reinterpret_cast<const float4*>(x + (size_t)bc * HW);
    float s = 0.f;
    for (int i = threadIdx.x; i < HW / 4; i += 256) {
        float4 v = p[i];
        s += (v.x + v.y) + (v.z + v.w);
    }
    __shared__ float sm[256];
    sm[threadIdx.x] = s;
    __syncthreads();
    for (int o = 128; o > 0; o >>= 1) {
        if (threadIdx.x < o) sm[threadIdx.x] += sm[threadIdx.x + o];
        __syncthreads();
    }
    if (threadIdx.x == 0) g_pooled[bc] = sm[0] * (1.f / HW);
}

// ---------------- 2) mix -> packed fp16x2 [b][st][kw][kp][oc] ----------------
__global__ __launch_bounds__(256) void mix_kernel(const float* __restrict__ weight,  // [E][OC][IC][3][3]
                                                  const float* __restrict__ fc_w,
                                                  const float* __restrict__ fc_b) {
    int b = blockIdx.x;
    __shared__ float r[NE];
    if (threadIdx.x < NE) {
        int e = threadIdx.x;
        float acc = fc_b[e];
        #pragma unroll 8
        for (int c = 0; c < CIN; c++) acc += g_pooled[b * CIN + c] * fc_w[e * CIN + c];
        r[e] = 1.f / (1.f + expf(-acc));
    }
    __syncthreads();
    float r0 = r[0], r1 = r[1], r2 = r[2], r3 = r[3];

    const size_t estride = (size_t)COUT * CIN * 9;
    const int NWORDS = 6 * 3 * 16 * COUT;   // 18432
    for (int idx = threadIdx.x; idx < NWORDS; idx += 256) {
        int oc = idx & 63;
        int kp = (idx >> 6) & 15;
        int t2 = idx >> 10;          // 0..17
        int kw = t2 % 3;
        int st = t2 / 3;             // ih*3 + kh
        int ih = st / 3, kh = st % 3;
        int tap = kh * 3 + kw;
        int ic = ih * 32 + 2 * kp;
        size_t s0 = ((size_t)oc * CIN + ic) * 9 + tap;
        size_t s1 = s0 + 9;          // ic + 1
        float v0 = r0 * weight[s0] + r1 * weight[s0 + estride]
                 + r2 * weight[s0 + 2 * estride] + r3 * weight[s0 + 3 * estride];
        float v1 = r0 * weight[s1] + r1 * weight[s1 + estride]
                 + r2 * weight[s1 + 2 * estride] + r3 * weight[s1 + 3 * estride];
        g_wmix[(size_t)b * NWORDS + idx] = packh2(v0, v1);
    }
}

// ---------------- 3) implicit-GEMM conv on mma.sync f16 ----------------
__global__ __launch_bounds__(256, 2) void conv_kernel(const float* __restrict__ x,
                                                      float* __restrict__ out) {
    __shared__ uint32_t A_h[2][16][RA];          // 17408 B
    __shared__ uint32_t B_h[2][3][16][RB];       // 27648 B

    const int tid = threadIdx.x;
    const int wid = tid >> 5;
    const int lid = tid & 31;
    const int g = lid >> 2;            // 0..7
    const int t = lid & 3;             // 0..3
    const int warpM = wid & 3;
    const int warpN = wid >> 2;

    const int w0 = blockIdx.x * MTILE;
    const int h  = blockIdx.y;
    const int b  = blockIdx.z;

    const float* xb = x + (size_t)b * CIN * HW;
    const uint32_t* wb = g_wmix + (size_t)b * (6 * 3 * 16 * COUT);

    uint32_t sbase;
    asm("{ .reg .u64 tt; cvta.to.shared.u64 tt, %1; cvt.u32.u64 %0, tt; }"
        : "=r"(sbase) : "l"(&B_h[0][0][0][0]));

    // ---- A staging geometry: thread -> (kp = tid>>4, c0 = tid&15) ----
    const int kpA = tid >> 4;          // 0..15
    const int c0A = tid & 15;          // 0..15 ; word cols c = c0A + 16*i

    float fa0[9], fa1[9];              // prefetched fp32 pairs (ic even/odd)

    auto ldA = [&](int st) {
        int ih = st / 3, kh = st % 3;
        int hp = h + kh - 1;
        bool hv = (unsigned)hp < HH;
        int hpc = hv ? hp : 0;
        const float* rowp = xb + (size_t)(ih * 32 + 2 * kpA) * HW + (size_t)hpc * WW + (w0 - 1);
        #pragma unroll
        for (int i = 0; i < 8; i++) {
            int c = c0A + 16 * i;              // 0..127
            int wp = w0 - 1 + c;
            bool v = hv && ((unsigned)wp < WW);
            fa0[i] = v ? __ldg(rowp + c) : 0.f;
            fa1[i] = v ? __ldg(rowp + c + HW) : 0.f;
        }
        {   // tail: c = 128,129 handled by c0A<2
            int c = c0A + 128;
            int wp = w0 - 1 + c;
            bool v = (c0A < 2) && hv && ((unsigned)wp < WW);
            fa0[8] = v ? __ldg(rowp + c) : 0.f;
            fa1[8] = v ? __ldg(rowp + c + HW) : 0.f;
        }
    };
    auto stA = [&](int buf) {
        #pragma unroll
        for (int i = 0; i < 8; i++)
            A_h[buf][kpA][c0A + 16 * i + 3] = packh2(fa0[i], fa1[i]);
        if (c0A < 2)
            A_h[buf][kpA][c0A + 128 + 3] = packh2(fa0[8], fa1[8]);
    };
    auto issueB = [&](int st, int buf) {
        const uint32_t* bsrc = wb + (size_t)st * 3072;
        #pragma unroll
        for (int i = 0; i < 3; i++) {
            int idx = tid + 256 * i;           // 0..767
            int row = idx >> 4;                // kw*16 + kp
            int q   = idx & 15;
            int kw  = row >> 4, kp = row & 15;
            uint32_t dst = sbase + (uint32_t)(((buf * B_BUFW) + kw * (16 * RB) + kp * RB + q * 4) * 4);
            asm volatile("cp.async.cg.shared.global [%0], [%1], 16;"
                         :: "r"(dst), "l"(bsrc + row * 64 + q * 4) : "memory");
        }
        asm volatile("cp.async.commit_group;" ::: "memory");
    };

    float d[2][4][4];
    #pragma unroll
    for (int mt = 0; mt < 2; mt++)
        #pragma unroll
        for (int nt = 0; nt < 4; nt++)
            #pragma unroll
            for (int k = 0; k < 4; k++) d[mt][nt][k] = 0.f;

    issueB(0, 0);
    ldA(0);

    for (int st = 0; st < 6; st++) {
        const int buf = st & 1;
        stA(buf);                                        // regs -> smem (A for st)
        asm volatile("cp.async.wait_group 0;" ::: "memory");
        __syncthreads();                                 // publish A + B
        if (st + 1 < 6) { issueB(st + 1, buf ^ 1); ldA(st + 1); }

        #pragma unroll
        for (int kw = 0; kw < 3; kw++) {
            const uint32_t* Bb = &B_h[buf][kw][0][0];
            #pragma unroll
            for (int ks = 0; ks < 2; ks++) {
                const int kb = ks * 8;                   // kp base for this k16-step
                uint32_t a[2][4];
                #pragma unroll
                for (int mt = 0; mt < 2; mt++) {
                    int mb = warpM * 32 + mt * 16 + g + kw + 3;
                    a[mt][0] = A_h[buf][kb + t][mb];
                    a[mt][1] = A_h[buf][kb + t][mb + 8];
                    a[mt][2] = A_h[buf][kb + t + 4][mb];
                    a[mt][3] = A_h[buf][kb + t + 4][mb + 8];
                }
                #pragma unroll
                for (int nt = 0; nt < 4; nt++) {
                    int nb = warpN * 32 + nt * 8 + g;
                    uint32_t b0 = Bb[(kb + t) * RB + nb];
                    uint32_t b1 = Bb[(kb + t + 4) * RB + nb];
                    #pragma unroll
                    for (int mt = 0; mt < 2; mt++)
                        mma_f16(d[mt][nt][0], d[mt][nt][1], d[mt][nt][2], d[mt][nt][3],
                                a[mt][0], a[mt][1], a[mt][2], a[mt][3], b0, b1);
                }
            }
        }
    }

    // ---- epilogue (identical D mapping to R7) ----
    #pragma unroll
    for (int nt = 0; nt < 4; nt++) {
        int oc = warpN * 32 + nt * 8 + 2 * t;
        #pragma unroll
        for (int mt = 0; mt < 2; mt++) {
            int pix = w0 + warpM * 32 + mt * 16 + g;
            float* o0 = out + (((size_t)b * COUT + oc) * HH + h) * WW + pix;
            float* o1 = o0 + HW;
            o0[0] = d[mt][nt][0];
            o1[0] = d[mt][nt][1];
            o0[8] = d[mt][nt][2];
            o1[8] = d[mt][nt][3];
        }
    }
}

// ---------------- launch ----------------
extern "C" void kernel_launch(void* const* d_in, const int* in_sizes, int n_in,
                              void* d_out, int out_size) {
    const float* inputs = (const float*)d_in[0];   // [16,64,256,256]
    const float* weight = (const float*)d_in[1];   // [4,64,64,3,3]
    const float* fc_w   = (const float*)d_in[2];   // [4,64]
    const float* fc_b   = (const float*)d_in[3];   // [4]
    float* out = (float*)d_out;                    // [16,64,256,256]

    pool_kernel<<<B_ * CIN, 256>>>(inputs);
    mix_kernel<<<B_, 256>>>(weight, fc_w, fc_b);
    conv_kernel<<<dim3(WW / MTILE, HH, B_), 256>>>(inputs, out);
}

// round 11
// speedup vs baseline: 4.7556x; 1.0966x over previous
#include <cuda_runtime.h>
#include <cuda_bf16.h>
#include <cuda_fp16.h>
#include <cstdint>

// CondConv2D: B=16, C=64, H=W=256, E=4, 3x3, pad=1.
//   1) pool_kernel : spatial mean
//   2) mix_kernel  : routing + expert mix -> packed fp16x2 weights
//                    g_wmix[b][stage6][kw3][kp16][oc64] (u32 = ic-pair)
//   3) conv_kernel : implicit GEMM on mma.sync.m16n8k16.f16 (f32 accum).
//      CTA tile = one full image row: M=256 pix x N=64 oc. 6 K-stages (ih x kh),
//      halo'd A row reused for kw=0..2 via column-shifted fragment reads.
//      A: register-staged LDG->cvt->STS, prefetched across stages.
//      B: cp.async double-buffered.

#define B_     16
#define CIN    64
#define COUT   64
#define HH     256
#define WW     256
#define HW     (HH * WW)
#define NE     4

#define RA 264           // A row: cols 0..257 = pix -1..256 ; 264 % 32 == 8 -> conflict-free
#define RB 72            // B row: 64 oc + pad ; 72 % 32 == 8
#define A_BUFW (16 * RA)         // 4224 u32 per buffer
#define B_BUFW (3 * 16 * RB)     // 3456 u32 per buffer
#define SMEM_BYTES ((2 * A_BUFW + 2 * B_BUFW) * 4)   // 61440

__device__ float g_pooled[B_ * CIN];
// packed fp16x2 mixed weights: [b][stage 6][kw 3][kp 16][oc 64]
__device__ __align__(16) uint32_t g_wmix[(size_t)B_ * 6 * 3 * 16 * COUT];

__device__ __forceinline__ void mma_f16(float& d0, float& d1, float& d2, float& d3,
                                        uint32_t a0, uint32_t a1, uint32_t a2, uint32_t a3,
                                        uint32_t b0, uint32_t b1) {
    asm volatile(
        "mma.sync.aligned.m16n8k16.row.col.f32.f16.f16.f32 "
        "{%0,%1,%2,%3}, {%4,%5,%6,%7}, {%8,%9}, {%0,%1,%2,%3};"
        : "+f"(d0), "+f"(d1), "+f"(d2), "+f"(d3)
        : "r"(a0), "r"(a1), "r"(a2), "r"(a3), "r"(b0), "r"(b1));
}

__device__ __forceinline__ uint32_t packh2(float lo, float hi) {
    __half2 h = __floats2half2_rn(lo, hi);
    return *reinterpret_cast<uint32_t*>(&h);
}

// ---------------- 1) pool ----------------
__global__ __launch_bounds__(256) void pool_kernel(const float* __restrict__ x) {
    int bc = blockIdx.x;
    const float4* p = reinterpret_cast<const float4*>(x + (size_t)bc * HW);
    float s = 0.f;
    for (int i = threadIdx.x; i < HW / 4; i += 256) {
        float4 v = p[i];
        s += (v.x + v.y) + (v.z + v.w);
    }
    __shared__ float sm[256];
    sm[threadIdx.x] = s;
    __syncthreads();
    for (int o = 128; o > 0; o >>= 1) {
        if (threadIdx.x < o) sm[threadIdx.x] += sm[threadIdx.x + o];
        __syncthreads();
    }
    if (threadIdx.x == 0) g_pooled[bc] = sm[0] * (1.f / HW);
}

// ---------------- 2) mix -> packed fp16x2 [b][st][kw][kp][oc] ----------------
__global__ __launch_bounds__(256) void mix_kernel(const float* __restrict__ weight,  // [E][OC][IC][3][3]
                                                  const float* __restrict__ fc_w,
                                                  const float* __restrict__ fc_b) {
    int b = blockIdx.x;
    __shared__ float r[NE];
    if (threadIdx.x < NE) {
        int e = threadIdx.x;
        float acc = fc_b[e];
        #pragma unroll 8
        for (int c = 0; c < CIN; c++) acc += g_pooled[b * CIN + c] * fc_w[e * CIN + c];
        r[e] = 1.f / (1.f + expf(-acc));
    }
    __syncthreads();
    float r0 = r[0], r1 = r[1], r2 = r[2], r3 = r[3];

    const size_t estride = (size_t)COUT * CIN * 9;
    const int NWORDS = 6 * 3 * 16 * COUT;   // 18432
    for (int idx = threadIdx.x; idx < NWORDS; idx += 256) {
        int oc = idx & 63;
        int kp = (idx >> 6) & 15;
        int t2 = idx >> 10;          // 0..17
        int kw = t2 % 3;
        int st = t2 / 3;             // ih*3 + kh
        int ih = st / 3, kh = st % 3;
        int tap = kh * 3 + kw;
        int ic = ih * 32 + 2 * kp;
        size_t s0 = ((size_t)oc * CIN + ic) * 9 + tap;
        size_t s1 = s0 + 9;          // ic + 1
        float v0 = r0 * weight[s0] + r1 * weight[s0 + estride]
                 + r2 * weight[s0 + 2 * estride] + r3 * weight[s0 + 3 * estride];
        float v1 = r0 * weight[s1] + r1 * weight[s1 + estride]
                 + r2 * weight[s1 + 2 * estride] + r3 * weight[s1 + 3 * estride];
        g_wmix[(size_t)b * NWORDS + idx] = packh2(v0, v1);
    }
}

// ---------------- 3) implicit-GEMM conv: M=256 (full row) x N=64 ----------------
__global__ __launch_bounds__(256, 2) void conv_kernel(const float* __restrict__ x,
                                                      float* __restrict__ out) {
    extern __shared__ uint32_t smem[];
    uint32_t* A_base = smem;                     // [2][16][RA]
    uint32_t* B_base = smem + 2 * A_BUFW;        // [2][3][16][RB]

    const int tid = threadIdx.x;
    const int wid = tid >> 5;
    const int lid = tid & 31;
    const int g = lid >> 2;            // 0..7
    const int t = lid & 3;             // 0..3
    const int warpM = wid & 3;         // 64-pix group
    const int warpN = wid >> 2;        // 32-oc group

    const int h = blockIdx.x;
    const int b = blockIdx.y;

    const float* xb = x + (size_t)b * CIN * HW;
    const uint32_t* wb = g_wmix + (size_t)b * (6 * 3 * 16 * COUT);

    uint32_t sbase;
    asm("{ .reg .u64 tt; cvta.to.shared.u64 tt, %1; cvt.u32.u64 %0, tt; }"
        : "=r"(sbase) : "l"(smem));

    // A staging: thread -> (kp = tid>>4, c0 = tid&15); cols c0 + 16*i, i<17
    const int kpA = tid >> 4;
    const int c0A = tid & 15;

    uint32_t au[17];                   // packed fp16x2 prefetch

    auto ldA = [&](int st) {
        int ih = st / 3, kh = st % 3;
        int hp = h + kh - 1;
        bool hv = (unsigned)hp < HH;
        int hpc = hv ? hp : 0;
        // col c in [0,258): pix wp = c - 1
        const float* rowp = xb + (size_t)(ih * 32 + 2 * kpA) * HW + (size_t)hpc * WW - 1;
        #pragma unroll
        for (int i = 0; i < 17; i++) {
            int c = c0A + 16 * i;
            int wp = c - 1;
            bool v = hv && ((unsigned)wp < WW) && (c < 258);
            float f0 = v ? __ldg(rowp + c) : 0.f;
            float f1 = v ? __ldg(rowp + c + HW) : 0.f;
            au[i] = packh2(f0, f1);
        }
    };
    auto stA = [&](int buf) {
        uint32_t* Ab = A_base + buf * A_BUFW + kpA * RA;
        #pragma unroll
        for (int i = 0; i < 16; i++) Ab[c0A + 16 * i] = au[i];
        if (c0A < 2) Ab[c0A + 256] = au[16];
    };
    auto issueB = [&](int st, int buf) {
        const uint32_t* bsrc = wb + (size_t)st * 3072;
        #pragma unroll
        for (int i = 0; i < 3; i++) {
            int idx = tid + 256 * i;           // 0..767
            int row = idx >> 4;                // kw*16 + kp
            int q   = idx & 15;
            int kw  = row >> 4, kp = row & 15;
            uint32_t dst = sbase + (uint32_t)((2 * A_BUFW + buf * B_BUFW + kw * (16 * RB) + kp * RB + q * 4) * 4);
            asm volatile("cp.async.cg.shared.global [%0], [%1], 16;"
                         :: "r"(dst), "l"(bsrc + row * 64 + q * 4) : "memory");
        }
        asm volatile("cp.async.commit_group;" ::: "memory");
    };

    float d[4][4][4];                  // [mt][nt][frag]
    #pragma unroll
    for (int mt = 0; mt < 4; mt++)
        #pragma unroll
        for (int nt = 0; nt < 4; nt++)
            #pragma unroll
            for (int k = 0; k < 4; k++) d[mt][nt][k] = 0.f;

    issueB(0, 0);
    ldA(0);

    for (int st = 0; st < 6; st++) {
        const int buf = st & 1;
        stA(buf);
        asm volatile("cp.async.wait_group 0;" ::: "memory");
        __syncthreads();
        if (st + 1 < 6) { issueB(st + 1, buf ^ 1); ldA(st + 1); }

        const uint32_t* Ab = A_base + buf * A_BUFW;
        #pragma unroll
        for (int kw = 0; kw < 3; kw++) {
            const uint32_t* Bb = B_base + buf * B_BUFW + kw * (16 * RB);
            #pragma unroll
            for (int ks = 0; ks < 2; ks++) {
                const int kb = ks * 8;
                // B fragments: reused across 4 mt tiles
                uint32_t bf[4][2];
                #pragma unroll
                for (int nt = 0; nt < 4; nt++) {
                    int nb = warpN * 32 + nt * 8 + g;
                    bf[nt][0] = Bb[(kb + t) * RB + nb];
                    bf[nt][1] = Bb[(kb + t + 4) * RB + nb];
                }
                #pragma unroll
                for (int mt = 0; mt < 4; mt++) {
                    int col = warpM * 64 + mt * 16 + g + kw;     // pix + kw
                    uint32_t a0 = Ab[(kb + t) * RA + col];
                    uint32_t a1 = Ab[(kb + t) * RA + col + 8];
                    uint32_t a2 = Ab[(kb + t + 4) * RA + col];
                    uint32_t a3 = Ab[(kb + t + 4) * RA + col + 8];
                    #pragma unroll
                    for (int nt = 0; nt < 4; nt++)
                        mma_f16(d[mt][nt][0], d[mt][nt][1], d[mt][nt][2], d[mt][nt][3],
                                a0, a1, a2, a3, bf[nt][0], bf[nt][1]);
                }
            }
        }
    }

    // ---- epilogue (same D-fragment mapping, mt now 0..3 over 64 pix) ----
    #pragma unroll
    for (int nt = 0; nt < 4; nt++) {
        int oc = warpN * 32 + nt * 8 + 2 * t;
        #pragma unroll
        for (int mt = 0; mt < 4; mt++) {
            int pix = warpM * 64 + mt * 16 + g;
            float* o0 = out + (((size_t)b * COUT + oc) * HH + h) * WW + pix;
            float* o1 = o0 + HW;
            o0[0] = d[mt][nt][0];
            o1[0] = d[mt][nt][1];
            o0[8] = d[mt][nt][2];
            o1[8] = d[mt][nt][3];
        }
    }
}

// ---------------- launch ----------------
extern "C" void kernel_launch(void* const* d_in, const int* in_sizes, int n_in,
                              void* d_out, int out_size) {
    const float* inputs = (const float*)d_in[0];   // [16,64,256,256]
    const float* weight = (const float*)d_in[1];   // [4,64,64,3,3]
    const float* fc_w   = (const float*)d_in[2];   // [4,64]
    const float* fc_b   = (const float*)d_in[3];   // [4]
    float* out = (float*)d_out;                    // [16,64,256,256]

    static int attr_set = 0;
    if (!attr_set) {
        cudaFuncSetAttribute(conv_kernel, cudaFuncAttributeMaxDynamicSharedMemorySize, SMEM_BYTES);
        attr_set = 1;
    }

    pool_kernel<<<B_ * CIN, 256>>>(inputs);
    mix_kernel<<<B_, 256>>>(weight, fc_w, fc_b);
    conv_kernel<<<dim3(HH, B_), 256, SMEM_BYTES>>>(inputs, out);
}

// round 12
// speedup vs baseline: 5.0246x; 1.0566x over previous
#include <cuda_runtime.h>
#include <cuda_bf16.h>
#include <cuda_fp16.h>
#include <cstdint>

// CondConv2D: B=16, C=64, H=W=256, E=4, 3x3, pad=1.
//   1) pool_kernel : spatial mean
//   2) mix_kernel  : routing + expert mix -> packed fp16x2 weights
//                    g_wmix[b][stage6][kw3][kp16][oc64]
//   3) conv_kernel : persistent row-sweeping implicit GEMM on mma.sync f16.
//      Per CTA (512 thr, 1/SM): B resident in smem (loaded once); A in a
//      4-slot x 2-ichalf ring with cross-row reuse (each input row loaded
//      once per CTA); ONE barrier per output row; M=256 x N=64 row tile.

#define B_     16
#define CIN    64
#define COUT   64
#define HH     256
#define WW     256
#define HW     (HH * WW)
#define NE     4

#define RA 264                    // A slot row stride (words); 264 % 32 == 8
#define RB 72                     // B row stride (words);      72 % 32 == 8
#define A_SLOTW (16 * RA)         // 4224 words per (ih, slot) tile
#define A_RINGW (8 * A_SLOTW)     // 33792 words (4 slots x 2 ih)
#define B_WORDS (288 * RB)        // 20736 words (6 st x 3 kw x 16 kp rows)
#define SMEM_BYTES ((A_RINGW + B_WORDS) * 4)   // 218112 B

#define CTAS_PER_B 9
#define ROWS_PER   29             // ceil(256/9)

__device__ float g_pooled[B_ * CIN];
// packed fp16x2 mixed weights: [b][stage 6][kw 3][kp 16][oc 64]
__device__ __align__(16) uint32_t g_wmix[(size_t)B_ * 6 * 3 * 16 * COUT];

__device__ __forceinline__ void mma_f16(float& d0, float& d1, float& d2, float& d3,
                                        uint32_t a0, uint32_t a1, uint32_t a2, uint32_t a3,
                                        uint32_t b0, uint32_t b1) {
    asm volatile(
        "mma.sync.aligned.m16n8k16.row.col.f32.f16.f16.f32 "
        "{%0,%1,%2,%3}, {%4,%5,%6,%7}, {%8,%9}, {%0,%1,%2,%3};"
        : "+f"(d0), "+f"(d1), "+f"(d2), "+f"(d3)
        : "r"(a0), "r"(a1), "r"(a2), "r"(a3), "r"(b0), "r"(b1));
}

__device__ __forceinline__ uint32_t packh2(float lo, float hi) {
    __half2 h = __floats2half2_rn(lo, hi);
    return *reinterpret_cast<uint32_t*>(&h);
}

// ---------------- 1) pool ----------------
__global__ __launch_bounds__(256) void pool_kernel(const float* __restrict__ x) {
    int bc = blockIdx.x;
    const float4* p = reinterpret_cast<const float4*>(x + (size_t)bc * HW);
    float s = 0.f;
    for (int i = threadIdx.x; i < HW / 4; i += 256) {
        float4 v = p[i];
        s += (v.x + v.y) + (v.z + v.w);
    }
    __shared__ float sm[256];
    sm[threadIdx.x] = s;
    __syncthreads();
    for (int o = 128; o > 0; o >>= 1) {
        if (threadIdx.x < o) sm[threadIdx.x] += sm[threadIdx.x + o];
        __syncthreads();
    }
    if (threadIdx.x == 0) g_pooled[bc] = sm[0] * (1.f / HW);
}

// ---------------- 2) mix -> packed fp16x2 [b][st][kw][kp][oc] ----------------
__global__ __launch_bounds__(256) void mix_kernel(const float* __restrict__ weight,  // [E][OC][IC][3][3]
                                                  const float* __restrict__ fc_w,
                                                  const float* __restrict__ fc_b) {
    int b = blockIdx.x;
    __shared__ float r[NE];
    if (threadIdx.x < NE) {
        int e = threadIdx.x;
        float acc = fc_b[e];
        #pragma unroll 8
        for (int c = 0; c < CIN; c++) acc += g_pooled[b * CIN + c] * fc_w[e * CIN + c];
        r[e] = 1.f / (1.f + expf(-acc));
    }
    __syncthreads();
    float r0 = r[0], r1 = r[1], r2 = r[2], r3 = r[3];

    const size_t estride = (size_t)COUT * CIN * 9;
    const int NWORDS = 6 * 3 * 16 * COUT;   // 18432
    for (int idx = threadIdx.x; idx < NWORDS; idx += 256) {
        int oc = idx & 63;
        int kp = (idx >> 6) & 15;
        int t2 = idx >> 10;          // 0..17
        int kw = t2 % 3;
        int st = t2 / 3;             // ih*3 + kh
        int ih = st / 3, kh = st % 3;
        int tap = kh * 3 + kw;
        int ic = ih * 32 + 2 * kp;
        size_t s0 = ((size_t)oc * CIN + ic) * 9 + tap;
        size_t s1 = s0 + 9;
        float v0 = r0 * weight[s0] + r1 * weight[s0 + estride]
                 + r2 * weight[s0 + 2 * estride] + r3 * weight[s0 + 3 * estride];
        float v1 = r0 * weight[s1] + r1 * weight[s1 + estride]
                 + r2 * weight[s1 + 2 * estride] + r3 * weight[s1 + 3 * estride];
        g_wmix[(size_t)b * NWORDS + idx] = packh2(v0, v1);
    }
}

// ---------------- 3) persistent row-sweeping conv ----------------
__global__ __launch_bounds__(512, 1) void conv_kernel(const float* __restrict__ x,
                                                      float* __restrict__ out) {
    extern __shared__ uint32_t smem[];
    uint32_t* A_ring = smem;                   // [2 ih][4 slot][16 kp][RA]
    uint32_t* B_s    = smem + A_RINGW;         // [288 rows][RB]

    const int tid = threadIdx.x;
    const int wid = tid >> 5;
    const int lid = tid & 31;
    const int g = lid >> 2;
    const int t = lid & 3;
    const int warpM = wid & 7;          // 32-pix group
    const int warpN = wid >> 3;         // 32-oc group

    const int b  = blockIdx.y;
    const int h0 = blockIdx.x * ROWS_PER;
    const int h1 = (h0 + ROWS_PER < HH) ? (h0 + ROWS_PER) : HH;

    const float* xb = x + (size_t)b * CIN * HW;
    const uint32_t* wb = g_wmix + (size_t)b * (6 * 3 * 16 * COUT);

    uint32_t sbaseB;
    asm("{ .reg .u64 tt; cvta.to.shared.u64 tt, %1; cvt.u32.u64 %0, tt; }"
        : "=r"(sbaseB) : "l"(B_s));

    // A staging: thread -> (kpA = wid, c0A = lid); cols c0A + 32*i
    const int kpA = tid >> 5;           // 0..15
    const int c0A = tid & 31;

    uint32_t au[9];
    auto ldA = [&](int ih, int row) {
        bool hv = (unsigned)row < HH;
        int hpc = hv ? row : 0;
        const float* rowp = xb + (size_t)(ih * 32 + 2 * kpA) * HW + (size_t)hpc * WW - 1;
        #pragma unroll
        for (int i = 0; i < 8; i++) {
            int c = c0A + 32 * i;       // 0..255 ; pix = c-1
            bool v = hv && (c >= 1);    // c-1 in [0,255) always when c>=1 (c<=255)
            float f0 = v ? __ldg(rowp + c) : 0.f;
            float f1 = v ? __ldg(rowp + c + HW) : 0.f;
            au[i] = packh2(f0, f1);
        }
        {   // cols 256,257 (pix 255,256): c0A<2
            int c = c0A + 256;
            bool v = hv && (c0A < 2) && (c - 1 < WW);   // c=256 -> pix 255 ok; c=257 -> pix 256 OOB
            float f0 = v ? __ldg(rowp + c) : 0.f;
            float f1 = v ? __ldg(rowp + c + HW) : 0.f;
            au[8] = packh2(f0, f1);
        }
    };
    auto stA = [&](int ih, int slot) {
        uint32_t* Ab = A_ring + (ih * 4 + slot) * A_SLOTW + kpA * RA;
        #pragma unroll
        for (int i = 0; i < 8; i++) Ab[c0A + 32 * i] = au[i];
        if (c0A < 2) Ab[c0A + 256] = au[8];
    };

    // ---- prologue: B (cp.async, once) + A rows h0-1..h0+1 ----
    #pragma unroll
    for (int i = 0; i < 9; i++) {
        int idx = tid + 512 * i;        // 0..4607
        int row = idx >> 4, q = idx & 15;
        uint32_t dst = sbaseB + (uint32_t)((row * RB + q * 4) * 4);
        asm volatile("cp.async.cg.shared.global [%0], [%1], 16;"
                     :: "r"(dst), "l"(wb + row * 64 + q * 4) : "memory");
    }
    asm volatile("cp.async.commit_group;" ::: "memory");
    #pragma unroll
    for (int r = 0; r < 3; r++) {
        int row = h0 - 1 + r;
        ldA(0, row); stA(0, row & 3);
        ldA(1, row); stA(1, row & 3);
    }
    asm volatile("cp.async.wait_group 0;" ::: "memory");

    float d[2][4][4];

    auto computeStage = [&](int ih, int kh, int h) {
        int slot = (h - 1 + kh) & 3;
        const uint32_t* Ab = A_ring + (ih * 4 + slot) * A_SLOTW;
        const int st = ih * 3 + kh;
        #pragma unroll
        for (int kw = 0; kw < 3; kw++) {
            const uint32_t* Bb = B_s + (size_t)((st * 3 + kw) * 16) * RB;
            #pragma unroll
            for (int ks = 0; ks < 2; ks++) {
                const int kb = ks * 8;
                uint32_t bf[4][2];
                #pragma unroll
                for (int nt = 0; nt < 4; nt++) {
                    int nb = warpN * 32 + nt * 8 + g;
                    bf[nt][0] = Bb[(kb + t) * RB + nb];
                    bf[nt][1] = Bb[(kb + t + 4) * RB + nb];
                }
                #pragma unroll
                for (int mt = 0; mt < 2; mt++) {
                    int col = warpM * 32 + mt * 16 + g + kw;
                    uint32_t a0 = Ab[(kb + t) * RA + col];
                    uint32_t a1 = Ab[(kb + t) * RA + col + 8];
                    uint32_t a2 = Ab[(kb + t + 4) * RA + col];
                    uint32_t a3 = Ab[(kb + t + 4) * RA + col + 8];
                    #pragma unroll
                    for (int nt = 0; nt < 4; nt++)
                        mma_f16(d[mt][nt][0], d[mt][nt][1], d[mt][nt][2], d[mt][nt][3],
                                a0, a1, a2, a3, bf[nt][0], bf[nt][1]);
                }
            }
        }
    };

    for (int h = h0; h < h1; h++) {
        __syncthreads();   // ring slot (h+2)&3 free; prefetched tiles published

        #pragma unroll
        for (int mt = 0; mt < 2; mt++)
            #pragma unroll
            for (int nt = 0; nt < 4; nt++)
                #pragma unroll
                for (int k = 0; k < 4; k++) d[mt][nt][k] = 0.f;

        const int pre = h + 2;          // input row needed by output row h+1

        ldA(0, pre);
        computeStage(0, 0, h);
        computeStage(0, 1, h);
        computeStage(0, 2, h);
        stA(0, pre & 3);

        ldA(1, pre);
        computeStage(1, 0, h);
        computeStage(1, 1, h);
        computeStage(1, 2, h);
        stA(1, pre & 3);

        // epilogue
        #pragma unroll
        for (int nt = 0; nt < 4; nt++) {
            int oc = warpN * 32 + nt * 8 + 2 * t;
            #pragma unroll
            for (int mt = 0; mt < 2; mt++) {
                int pix = warpM * 32 + mt * 16 + g;
                float* o0 = out + (((size_t)b * COUT + oc) * HH + h) * WW + pix;
                float* o1 = o0 + HW;
                o0[0] = d[mt][nt][0];
                o1[0] = d[mt][nt][1];
                o0[8] = d[mt][nt][2];
                o1[8] = d[mt][nt][3];
            }
        }
    }
}

// ---------------- launch ----------------
extern "C" void kernel_launch(void* const* d_in, const int* in_sizes, int n_in,
                              void* d_out, int out_size) {
    const float* inputs = (const float*)d_in[0];   // [16,64,256,256]
    const float* weight = (const float*)d_in[1];   // [4,64,64,3,3]
    const float* fc_w   = (const float*)d_in[2];   // [4,64]
    const float* fc_b   = (const float*)d_in[3];   // [4]
    float* out = (float*)d_out;                    // [16,64,256,256]

    static int attr_set = 0;
    if (!attr_set) {
        cudaFuncSetAttribute(conv_kernel, cudaFuncAttributeMaxDynamicSharedMemorySize, SMEM_BYTES);
        attr_set = 1;
    }

    pool_kernel<<<B_ * CIN, 256>>>(inputs);
    mix_kernel<<<B_, 256>>>(weight, fc_w, fc_b);
    conv_kernel<<<dim3(CTAS_PER_B, B_), 512, SMEM_BYTES>>>(inputs, out);
}

// round 13
// speedup vs baseline: 5.6108x; 1.1167x over previous
#include <cuda_runtime.h>
#include <cuda_bf16.h>
#include <cuda_fp16.h>
#include <cstdint>

// CondConv2D: B=16, C=64, H=W=256, E=4, 3x3, pad=1.
//   1) pool_kernel : spatial mean
//   2) mix_kernel  : routing + expert mix -> packed fp16x2 weights (coalesced reads)
//   3) conv_kernel : persistent implicit GEMM on mma.sync f16, 148 CTAs sweeping
//      a globally balanced (b,h) row list. B resident in smem per batch-segment;
//      A in a 4-slot x 2-ichalf ring (each input row loaded once per segment);
//      one barrier per output row; M=256 x N=64 row tile.

#define B_     16
#define CIN    64
#define COUT   64
#define HH     256
#define WW     256
#define HW     (HH * WW)
#define NE     4
#define NCTA   148

#define RA 264                    // A slot row stride (words); 264 % 32 == 8
#define RB 72                     // B row stride (words);      72 % 32 == 8
#define A_SLOTW (16 * RA)         // 4224 words per (ih, slot) tile
#define A_RINGW (8 * A_SLOTW)     // 33792 words (4 slots x 2 ih)
#define B_WORDS (288 * RB)        // 20736 words (6 st x 3 kw x 16 kp rows)
#define SMEM_BYTES ((A_RINGW + B_WORDS) * 4)   // 218112 B

__device__ float g_pooled[B_ * CIN];
// packed fp16x2 mixed weights: [b][stage 6][kw 3][kp 16][oc 64]
__device__ __align__(16) uint32_t g_wmix[(size_t)B_ * 6 * 3 * 16 * COUT];

__device__ __forceinline__ void mma_f16(float& d0, float& d1, float& d2, float& d3,
                                        uint32_t a0, uint32_t a1, uint32_t a2, uint32_t a3,
                                        uint32_t b0, uint32_t b1) {
    asm volatile(
        "mma.sync.aligned.m16n8k16.row.col.f32.f16.f16.f32 "
        "{%0,%1,%2,%3}, {%4,%5,%6,%7}, {%8,%9}, {%0,%1,%2,%3};"
        : "+f"(d0), "+f"(d1), "+f"(d2), "+f"(d3)
        : "r"(a0), "r"(a1), "r"(a2), "r"(a3), "r"(b0), "r"(b1));
}

__device__ __forceinline__ uint32_t packh2(float lo, float hi) {
    __half2 h = __floats2half2_rn(lo, hi);
    return *reinterpret_cast<uint32_t*>(&h);
}

// ---------------- 1) pool ----------------
__global__ __launch_bounds__(256) void pool_kernel(const float* __restrict__ x) {
    int bc = blockIdx.x;
    const float4* p = reinterpret_cast<const float4*>(x + (size_t)bc * HW);
    float s = 0.f;
    for (int i = threadIdx.x; i < HW / 4; i += 256) {
        float4 v = p[i];
        s += (v.x + v.y) + (v.z + v.w);
    }
    __shared__ float sm[256];
    sm[threadIdx.x] = s;
    __syncthreads();
    for (int o = 128; o > 0; o >>= 1) {
        if (threadIdx.x < o) sm[threadIdx.x] += sm[threadIdx.x + o];
        __syncthreads();
    }
    if (threadIdx.x == 0) g_pooled[bc] = sm[0] * (1.f / HW);
}

// ---------------- 2) mix (coalesced reads) ----------------
__global__ __launch_bounds__(256) void mix_kernel(const float* __restrict__ weight,  // [E][OC][IC][3][3]
                                                  const float* __restrict__ fc_w,
                                                  const float* __restrict__ fc_b) {
    int b = blockIdx.x;
    __shared__ float r[NE];
    if (threadIdx.x < NE) {
        int e = threadIdx.x;
        float acc = fc_b[e];
        #pragma unroll 8
        for (int c = 0; c < CIN; c++) acc += g_pooled[b * CIN + c] * fc_w[e * CIN + c];
        r[e] = 1.f / (1.f + expf(-acc));
    }
    __syncthreads();
    float r0 = r[0], r1 = r[1], r2 = r[2], r3 = r[3];

    const size_t estride = (size_t)COUT * CIN * 9;   // 36864
    uint32_t* ob = g_wmix + (size_t)b * (6 * 3 * 16 * COUT);
    // widx -> (oc, ih, kp, tap); threads sweep (kp,tap) fastest so that the
    // 8 source reads per word are near-contiguous across a warp.
    for (int widx = threadIdx.x; widx < 64 * 288; widx += 256) {
        int oc   = widx / 288;
        int rem  = widx - oc * 288;
        int ih   = rem / 144;
        int rem2 = rem - ih * 144;
        int kp   = rem2 / 9;
        int tap  = rem2 - kp * 9;
        int kh = tap / 3, kw = tap - kh * 3;
        int ic = ih * 32 + 2 * kp;
        size_t s0 = ((size_t)oc * CIN + ic) * 9 + tap;
        size_t s1 = s0 + 9;
        float v0 = r0 * weight[s0] + r1 * weight[s0 + estride]
                 + r2 * weight[s0 + 2 * estride] + r3 * weight[s0 + 3 * estride];
        float v1 = r0 * weight[s1] + r1 * weight[s1 + estride]
                 + r2 * weight[s1 + 2 * estride] + r3 * weight[s1 + 3 * estride];
        int st = ih * 3 + kh;
        ob[((st * 3 + kw) * 16 + kp) * 64 + oc] = packh2(v0, v1);
    }
}

// ---------------- 3) persistent globally-balanced conv ----------------
__global__ __launch_bounds__(512, 1) void conv_kernel(const float* __restrict__ x,
                                                      float* __restrict__ out) {
    extern __shared__ uint32_t smem[];
    uint32_t* A_ring = smem;                   // [2 ih][4 slot][16 kp][RA]
    uint32_t* B_s    = smem + A_RINGW;         // [288 rows][RB]

    const int tid = threadIdx.x;
    const int wid = tid >> 5;
    const int lid = tid & 31;
    const int g = lid >> 2;
    const int t = lid & 3;
    const int warpM = wid & 7;          // 32-pix group
    const int warpN = wid >> 3;         // 32-oc group

    uint32_t sbaseB;
    asm("{ .reg .u64 tt; cvta.to.shared.u64 tt, %1; cvt.u32.u64 %0, tt; }"
        : "=r"(sbaseB) : "l"(B_s));

    // A staging: thread -> (kpA = tid>>5, c0A = tid&31); cols c0A + 32*i
    const int kpA = tid >> 5;           // 0..15
    const int c0A = tid & 31;

    const float* xb = x;                // set per segment
    const uint32_t* wb = g_wmix;
    int b = 0;

    uint32_t au[9];
    auto ldA = [&](int ih, int row) {
        bool hv = (unsigned)row < HH;
        int hpc = hv ? row : 0;
        const float* rowp = xb + (size_t)(ih * 32 + 2 * kpA) * HW + (size_t)hpc * WW - 1;
        #pragma unroll
        for (int i = 0; i < 8; i++) {
            int c = c0A + 32 * i;       // 0..255 ; pix = c-1
            bool v = hv && (c >= 1);
            float f0 = v ? __ldg(rowp + c) : 0.f;
            float f1 = v ? __ldg(rowp + c + HW) : 0.f;
            au[i] = packh2(f0, f1);
        }
        {   // cols 256,257 (pix 255,256): c0A<2 ; pix 256 OOB -> zero
            int c = c0A + 256;
            bool v = hv && (c0A < 2) && (c - 1 < WW);
            float f0 = v ? __ldg(rowp + c) : 0.f;
            float f1 = v ? __ldg(rowp + c + HW) : 0.f;
            au[8] = packh2(f0, f1);
        }
    };
    auto stA = [&](int ih, int slot) {
        uint32_t* Ab = A_ring + (ih * 4 + slot) * A_SLOTW + kpA * RA;
        #pragma unroll
        for (int i = 0; i < 8; i++) Ab[c0A + 32 * i] = au[i];
        if (c0A < 2) Ab[c0A + 256] = au[8];
    };

    float d[2][4][4];

    auto computeStage = [&](int ih, int kh, int h) {
        int slot = (h - 1 + kh) & 3;
        const uint32_t* Ab = A_ring + (ih * 4 + slot) * A_SLOTW;
        const int st = ih * 3 + kh;
        #pragma unroll
        for (int kw = 0; kw < 3; kw++) {
            const uint32_t* Bb = B_s + (size_t)((st * 3 + kw) * 16) * RB;
            #pragma unroll
            for (int ks = 0; ks < 2; ks++) {
                const int kb = ks * 8;
                uint32_t bf[4][2];
                #pragma unroll
                for (int nt = 0; nt < 4; nt++) {
                    int nb = warpN * 32 + nt * 8 + g;
                    bf[nt][0] = Bb[(kb + t) * RB + nb];
                    bf[nt][1] = Bb[(kb + t + 4) * RB + nb];
                }
                #pragma unroll
                for (int mt = 0; mt < 2; mt++) {
                    int col = warpM * 32 + mt * 16 + g + kw;
                    uint32_t a0 = Ab[(kb + t) * RA + col];
                    uint32_t a1 = Ab[(kb + t) * RA + col + 8];
                    uint32_t a2 = Ab[(kb + t + 4) * RA + col];
                    uint32_t a3 = Ab[(kb + t + 4) * RA + col + 8];
                    #pragma unroll
                    for (int nt = 0; nt < 4; nt++)
                        mma_f16(d[mt][nt][0], d[mt][nt][1], d[mt][nt][2], d[mt][nt][3],
                                a0, a1, a2, a3, bf[nt][0], bf[nt][1]);
                }
            }
        }
    };

    // ---- globally balanced row slice over (b, h) ----
    const int TOT = B_ * HH;                       // 4096
    int r0 = (TOT * (int)blockIdx.x) / NCTA;
    int r1 = (TOT * ((int)blockIdx.x + 1)) / NCTA;
    int r = r0;

    while (r < r1) {
        b = r >> 8;
        int h0 = r & 255;
        int segEnd = (r1 < ((b + 1) << 8)) ? r1 : ((b + 1) << 8);
        int h1 = segEnd - (b << 8);
        xb = x + (size_t)b * CIN * HW;
        wb = g_wmix + (size_t)b * (6 * 3 * 16 * COUT);

        __syncthreads();   // previous segment finished reading B_s / ring

        // B for this batch (cp.async, once per segment)
        #pragma unroll
        for (int i = 0; i < 9; i++) {
            int idx = tid + 512 * i;        // 0..4607
            int row = idx >> 4, q = idx & 15;
            uint32_t dst = sbaseB + (uint32_t)((row * RB + q * 4) * 4);
            asm volatile("cp.async.cg.shared.global [%0], [%1], 16;"
                         :: "r"(dst), "l"(wb + row * 64 + q * 4) : "memory");
        }
        asm volatile("cp.async.commit_group;" ::: "memory");

        // A prologue: rows h0-1 .. h0+1
        #pragma unroll
        for (int rr = 0; rr < 3; rr++) {
            int row = h0 - 1 + rr;
            ldA(0, row); stA(0, row & 3);
            ldA(1, row); stA(1, row & 3);
        }
        asm volatile("cp.async.wait_group 0;" ::: "memory");

        for (int h = h0; h < h1; h++) {
            __syncthreads();   // ring slot (h+2)&3 free; staged tiles published

            #pragma unroll
            for (int mt = 0; mt < 2; mt++)
                #pragma unroll
                for (int nt = 0; nt < 4; nt++)
                    #pragma unroll
                    for (int k = 0; k < 4; k++) d[mt][nt][k] = 0.f;

            const int pre = h + 2;

            ldA(0, pre);
            computeStage(0, 0, h);
            computeStage(0, 1, h);
            computeStage(0, 2, h);
            stA(0, pre & 3);

            ldA(1, pre);
            computeStage(1, 0, h);
            computeStage(1, 1, h);
            computeStage(1, 2, h);
            stA(1, pre & 3);

            // epilogue
            #pragma unroll
            for (int nt = 0; nt < 4; nt++) {
                int oc = warpN * 32 + nt * 8 + 2 * t;
                #pragma unroll
                for (int mt = 0; mt < 2; mt++) {
                    int pix = warpM * 32 + mt * 16 + g;
                    float* o0 = out + (((size_t)b * COUT + oc) * HH + h) * WW + pix;
                    float* o1 = o0 + HW;
                    o0[0] = d[mt][nt][0];
                    o1[0] = d[mt][nt][1];
                    o0[8] = d[mt][nt][2];
                    o1[8] = d[mt][nt][3];
                }
            }
        }
        r = segEnd;
    }
}

// ---------------- launch ----------------
extern "C" void kernel_launch(void* const* d_in, const int* in_sizes, int n_in,
                              void* d_out, int out_size) {
    const float* inputs = (const float*)d_in[0];   // [16,64,256,256]
    const float* weight = (const float*)d_in[1];   // [4,64,64,3,3]
    const float* fc_w   = (const float*)d_in[2];   // [4,64]
    const float* fc_b   = (const float*)d_in[3];   // [4]
    float* out = (float*)d_out;                    // [16,64,256,256]

    static int attr_set = 0;
    if (!attr_set) {
        cudaFuncSetAttribute(conv_kernel, cudaFuncAttributeMaxDynamicSharedMemorySize, SMEM_BYTES);
        attr_set = 1;
    }

    pool_kernel<<<B_ * CIN, 256>>>(inputs);
    mix_kernel<<<B_, 256>>>(weight, fc_w, fc_b);
    conv_kernel<<<NCTA, 512, SMEM_BYTES>>>(inputs, out);
}

// round 16
// speedup vs baseline: 6.2808x; 1.1194x over previous
#include <cuda_runtime.h>
#include <cuda_bf16.h>
#include <cuda_fp16.h>
#include <cstdint>

// CondConv2D: B=16, C=64, H=W=256, E=4, 3x3, pad=1.
// Single fused persistent kernel, 148 CTAs x 512 threads:
//   Phase 1: spatial-mean pool (balanced plane partition, deterministic)
//   [grid barrier]
//   Phase 2: routing (duplicated, trivial) + expert-mix -> g_wmix (all CTAs)
//   [grid barrier]
//   Phase 3: persistent implicit-GEMM conv on mma.sync.m16n8k16.f16 (f32 acc),
//            globally balanced (b,h) row sweep; B resident in smem per batch
//            segment; A in 4-slot x 2-ichalf ring (LDG.64 staging); one
//            barrier per output row; M=256 x N=64 row tile.
// Grid barriers use monotone tickets (each launch adds exactly NCTA) so CUDA
// graph replays are safe; 148 CTAs at 213KB smem are 1/SM and co-resident.

#define B_     16
#define CIN    64
#define COUT   64
#define HH     256
#define WW     256
#define HW     (HH * WW)
#define NE     4
#define NCTA   148

#define RA 264                    // A slot row stride (words); 264 % 32 == 8
#define RB 72                     // B row stride (words);      72 % 32 == 8
#define A_SLOTW (16 * RA)         // 4224 words per (ih, slot) tile
#define A_RINGW (8 * A_SLOTW)     // 33792 words (4 slots x 2 ih)
#define B_WORDS (288 * RB)        // 20736 words (6 st x 3 kw x 16 kp rows)
#define SMEM_BYTES ((A_RINGW + B_WORDS) * 4)   // 218112 B

#define MIXW (6 * 3 * 16 * COUT)  // 18432 words per batch

__device__ float g_pooled[B_ * CIN];
__device__ __align__(16) uint32_t g_wmix[(size_t)B_ * MIXW];
__device__ unsigned g_bar0, g_bar1;   // monotone barrier tickets

__device__ __forceinline__ void mma_f16(float& d0, float& d1, float& d2, float& d3,
                                        uint32_t a0, uint32_t a1, uint32_t a2, uint32_t a3,
                                        uint32_t b0, uint32_t b1) {
    asm volatile(
        "mma.sync.aligned.m16n8k16.row.col.f32.f16.f16.f32 "
        "{%0,%1,%2,%3}, {%4,%5,%6,%7}, {%8,%9}, {%0,%1,%2,%3};"
        : "+f"(d0), "+f"(d1), "+f"(d2), "+f"(d3)
        : "r"(a0), "r"(a1), "r"(a2), "r"(a3), "r"(b0), "r"(b1));
}

__device__ __forceinline__ uint32_t packh2(float lo, float hi) {
    __half2 h = __floats2half2_rn(lo, hi);
    return *reinterpret_cast<uint32_t*>(&h);
}

__device__ __forceinline__ void grid_barrier(unsigned* bar) {
    __syncthreads();
    if (threadIdx.x == 0) {
        __threadfence();
        unsigned ticket = atomicAdd(bar, 1u);
        unsigned target = (ticket / NCTA + 1u) * NCTA;
        while (*(volatile unsigned*)bar < target) { }
        __threadfence();
    }
    __syncthreads();
}

__global__ __launch_bounds__(512, 1) void fused_kernel(const float* __restrict__ x,
                                                       const float* __restrict__ weight,
                                                       const float* __restrict__ fc_w,
                                                       const float* __restrict__ fc_b,
                                                       float* __restrict__ out) {
    extern __shared__ uint32_t smem[];
    const int tid = threadIdx.x;
    const int wid = tid >> 5;
    const int lid = tid & 31;
    const int cta = blockIdx.x;

    // ================= Phase 1: pool =================
    {
        float* scr = (float*)smem;                  // 16-float scratch
        int p0 = (B_ * CIN * cta) / NCTA;
        int p1 = (B_ * CIN * (cta + 1)) / NCTA;
        for (int p = p0; p < p1; p++) {
            const float4* xp = (const float4*)(x + (size_t)p * HW);
            float s = 0.f;
            #pragma unroll 8
            for (int i = tid; i < HW / 4; i += 512) {
                float4 v = __ldg(xp + i);
                s += (v.x + v.y) + (v.z + v.w);
            }
            #pragma unroll
            for (int o = 16; o > 0; o >>= 1) s += __shfl_xor_sync(0xFFFFFFFF, s, o);
            if (lid == 0) scr[wid] = s;
            __syncthreads();
            if (wid == 0) {
                float v = (lid < 16) ? scr[lid] : 0.f;
                #pragma unroll
                for (int o = 8; o > 0; o >>= 1) v += __shfl_xor_sync(0xFFFFFFFF, v, o);
                if (lid == 0) g_pooled[p] = v * (1.f / HW);
            }
            __syncthreads();
        }
    }
    grid_barrier(&g_bar0);

    // ================= Phase 2: routing + mix =================
    {
        float* r_all = (float*)smem;                // [16 b][4 e]
        if (tid < 64) {
            int b = tid >> 2, e = tid & 3;
            float acc = fc_b[e];
            #pragma unroll 8
            for (int c = 0; c < CIN; c++) acc += g_pooled[b * CIN + c] * fc_w[e * CIN + c];
            r_all[tid] = 1.f / (1.f + expf(-acc));
        }
        __syncthreads();

        const size_t estride = (size_t)COUT * CIN * 9;   // 36864
        const int TOTW = B_ * MIXW;                      // 294912
        int w0 = (int)(((long long)TOTW * cta) / NCTA);
        int w1 = (int)(((long long)TOTW * (cta + 1)) / NCTA);
        for (int gw = w0 + tid; gw < w1; gw += 512) {
            int b    = gw / MIXW;
            int widx = gw - b * MIXW;
            int oc   = widx / 288;
            int rem  = widx - oc * 288;
            int ih   = rem / 144;
            int rem2 = rem - ih * 144;
            int kp   = rem2 / 9;
            int tap  = rem2 - kp * 9;
            int kh = tap / 3, kw = tap - kh * 3;
            int ic = ih * 32 + 2 * kp;
            float r0 = r_all[b * 4 + 0], r1 = r_all[b * 4 + 1];
            float r2 = r_all[b * 4 + 2], r3 = r_all[b * 4 + 3];
            size_t s0 = ((size_t)oc * CIN + ic) * 9 + tap;
            size_t s1 = s0 + 9;
            float v0 = r0 * weight[s0] + r1 * weight[s0 + estride]
                     + r2 * weight[s0 + 2 * estride] + r3 * weight[s0 + 3 * estride];
            float v1 = r0 * weight[s1] + r1 * weight[s1 + estride]
                     + r2 * weight[s1 + 2 * estride] + r3 * weight[s1 + 3 * estride];
            int st = ih * 3 + kh;
            g_wmix[(size_t)b * MIXW + ((st * 3 + kw) * 16 + kp) * 64 + oc] = packh2(v0, v1);
        }
    }
    grid_barrier(&g_bar1);

    // ================= Phase 3: conv =================
    uint32_t* A_ring = smem;                   // [2 ih][4 slot][16 kp][RA]
    uint32_t* B_s    = smem + A_RINGW;         // [288 rows][RB]

    const int g = lid >> 2;
    const int t = lid & 3;
    const int warpM = wid & 7;          // 32-pix group
    const int warpN = wid >> 3;         // 32-oc group

    uint32_t sbaseB;
    asm("{ .reg .u64 tt; cvta.to.shared.u64 tt, %1; cvt.u32.u64 %0, tt; }"
        : "=r"(sbaseB) : "l"(B_s));

    const int kpA = tid >> 5;           // 0..15
    const int c0A = tid & 31;           // pair index base

    const float* xb = x;
    const uint32_t* wb = g_wmix;
    int b = 0;

    uint32_t au[8];
    auto ldA = [&](int ih, int row) {
        bool hv = (unsigned)row < HH;
        int hpc = hv ? row : 0;
        const float2* r0p = (const float2*)(xb + (size_t)(ih * 32 + 2 * kpA) * HW + (size_t)hpc * WW);
        const float2* r1p = r0p + HW / 2;
        #pragma unroll
        for (int i = 0; i < 4; i++) {
            int j = c0A + 32 * i;       // aligned pixel pair (2j, 2j+1)
            float2 v0 = hv ? __ldg(r0p + j) : make_float2(0.f, 0.f);
            float2 v1 = hv ? __ldg(r1p + j) : make_float2(0.f, 0.f);
            au[2 * i]     = packh2(v0.x, v1.x);   // smem col 2j+1 (pix 2j)
            au[2 * i + 1] = packh2(v0.y, v1.y);   // smem col 2j+2 (pix 2j+1)
        }
    };
    auto stA = [&](int ih, int slot) {
        uint32_t* Ab = A_ring + (ih * 4 + slot) * A_SLOTW + kpA * RA;
        #pragma unroll
        for (int i = 0; i < 4; i++) {
            int j = c0A + 32 * i;
            Ab[2 * j + 1] = au[2 * i];
            Ab[2 * j + 2] = au[2 * i + 1];
        }
        if (c0A == 0) { Ab[0] = 0u; Ab[257] = 0u; }   // pix -1 / pix 256: always OOB
    };

    float d[2][4][4];

    auto computeStage = [&](int ih, int kh, int h) {
        int slot = (h - 1 + kh) & 3;
        const uint32_t* Ab = A_ring + (ih * 4 + slot) * A_SLOTW;
        const int st = ih * 3 + kh;
        #pragma unroll
        for (int kw = 0; kw < 3; kw++) {
            const uint32_t* Bb = B_s + (size_t)((st * 3 + kw) * 16) * RB;
            #pragma unroll
            for (int ks = 0; ks < 2; ks++) {
                const int kb = ks * 8;
                uint32_t bf[4][2];
                #pragma unroll
                for (int nt = 0; nt < 4; nt++) {
                    int nb = warpN * 32 + nt * 8 + g;
                    bf[nt][0] = Bb[(kb + t) * RB + nb];
                    bf[nt][1] = Bb[(kb + t + 4) * RB + nb];
                }
                #pragma unroll
                for (int mt = 0; mt < 2; mt++) {
                    int col = warpM * 32 + mt * 16 + g + kw;
                    uint32_t a0 = Ab[(kb + t) * RA + col];
                    uint32_t a1 = Ab[(kb + t) * RA + col + 8];
                    uint32_t a2 = Ab[(kb + t + 4) * RA + col];
                    uint32_t a3 = Ab[(kb + t + 4) * RA + col + 8];
                    #pragma unroll
                    for (int nt = 0; nt < 4; nt++)
                        mma_f16(d[mt][nt][0], d[mt][nt][1], d[mt][nt][2], d[mt][nt][3],
                                a0, a1, a2, a3, bf[nt][0], bf[nt][1]);
                }
            }
        }
    };

    const int TOT = B_ * HH;                       // 4096
    int r0 = (TOT * cta) / NCTA;
    int r1 = (TOT * (cta + 1)) / NCTA;
    int r = r0;

    while (r < r1) {
        b = r >> 8;
        int h0 = r & 255;
        int segEnd = (r1 < ((b + 1) << 8)) ? r1 : ((b + 1) << 8);
        int h1 = segEnd - (b << 8);
        xb = x + (size_t)b * CIN * HW;
        wb = g_wmix + (size_t)b * MIXW;

        __syncthreads();   // previous segment finished reading B_s / ring

        // B for this batch (cp.async, once per segment)
        #pragma unroll
        for (int i = 0; i < 9; i++) {
            int idx = tid + 512 * i;        // 0..4607
            int row = idx >> 4, q = idx & 15;
            uint32_t dst = sbaseB + (uint32_t)((row * RB + q * 4) * 4);
            asm volatile("cp.async.cg.shared.global [%0], [%1], 16;"
                         :: "r"(dst), "l"(wb + row * 64 + q * 4) : "memory");
        }
        asm volatile("cp.async.commit_group;" ::: "memory");

        // A prologue: rows h0-1 .. h0+1
        #pragma unroll
        for (int rr = 0; rr < 3; rr++) {
            int row = h0 - 1 + rr;
            ldA(0, row); stA(0, row & 3);
            ldA(1, row); stA(1, row & 3);
        }
        asm volatile("cp.async.wait_group 0;" ::: "memory");

        for (int h = h0; h < h1; h++) {
            __syncthreads();   // ring slot (h+2)&3 free; staged tiles published

            #pragma unroll
            for (int mt = 0; mt < 2; mt++)
                #pragma unroll
                for (int nt = 0; nt < 4; nt++)
                    #pragma unroll
                    for (int k = 0; k < 4; k++) d[mt][nt][k] = 0.f;

            const int pre = h + 2;

            ldA(0, pre);
            computeStage(0, 0, h);
            computeStage(0, 1, h);
            computeStage(0, 2, h);
            stA(0, pre & 3);

            ldA(1, pre);
            computeStage(1, 0, h);
            computeStage(1, 1, h);
            computeStage(1, 2, h);
            stA(1, pre & 3);

            // epilogue
            #pragma unroll
            for (int nt = 0; nt < 4; nt++) {
                int oc = warpN * 32 + nt * 8 + 2 * t;
                #pragma unroll
                for (int mt = 0; mt < 2; mt++) {
                    int pix = warpM * 32 + mt * 16 + g;
                    float* o0 = out + (((size_t)b * COUT + oc) * HH + h) * WW + pix;
                    float* o1 = o0 + HW;
                    o0[0] = d[mt][nt][0];
                    o1[0] = d[mt][nt][1];
                    o0[8] = d[mt][nt][2];
                    o1[8] = d[mt][nt][3];
                }
            }
        }
        r = segEnd;
    }
}

// ---------------- launch ----------------
extern "C" void kernel_launch(void* const* d_in, const int* in_sizes, int n_in,
                              void* d_out, int out_size) {
    const float* inputs = (const float*)d_in[0];   // [16,64,256,256]
    const float* weight = (const float*)d_in[1];   // [4,64,64,3,3]
    const float* fc_w   = (const float*)d_in[2];   // [4,64]
    const float* fc_b   = (const float*)d_in[3];   // [4]
    float* out = (float*)d_out;                    // [16,64,256,256]

    static int attr_set = 0;
    if (!attr_set) {
        cudaFuncSetAttribute(fused_kernel, cudaFuncAttributeMaxDynamicSharedMemorySize, SMEM_BYTES);
        attr_set = 1;
    }

    fused_kernel<<<NCTA, 512, SMEM_BYTES>>>(inputs, weight, fc_w, fc_b, out);
}